// round 11
// baseline (speedup 1.0000x reference)
#include <cuda_runtime.h>
#include <cuda_bf16.h>
#include <math.h>
#include <stdint.h>

#define BATCH 4
#define SEQ 1024
#define DMODEL 768
#define NHEAD 12
#define DHEAD 64
#define BN (BATCH*SEQ)

// ---- scratch (static device globals; no allocation) ----
__device__ float g_attn[(size_t)BATCH * NHEAD * SEQ * SEQ];        // fp32 S
__device__ __nv_bfloat16 g_ah[(size_t)BATCH * NHEAD * SEQ * SEQ];  // A hi
__device__ __nv_bfloat16 g_al[(size_t)BATCH * NHEAD * SEQ * SEQ];  // A lo
__device__ __nv_bfloat16 g_qh[BN * DMODEL], g_ql[BN * DMODEL];
__device__ __nv_bfloat16 g_kh[BN * DMODEL], g_kl[BN * DMODEL];
__device__ __nv_bfloat16 g_vh[BN * DMODEL], g_vl[BN * DMODEL];
__device__ __nv_bfloat16 g_xh[BN * DMODEL], g_xl[BN * DMODEL];
__device__ __nv_bfloat16 g_wh[3 * DMODEL * DMODEL], g_wl[3 * DMODEL * DMODEL];

// ============================================================
// helpers
// ============================================================
__device__ __forceinline__ uint32_t smem_u32(const void* p) {
    return (uint32_t)__cvta_generic_to_shared(p);
}

__device__ __forceinline__ void cp16(void* smem, const void* gmem) {
    asm volatile("cp.async.cg.shared.global [%0], [%1], 16;\n" ::"r"(smem_u32(smem)),
                 "l"(gmem));
}
#define CP_COMMIT asm volatile("cp.async.commit_group;\n" ::)
#define CP_WAIT0 asm volatile("cp.async.wait_group 0;\n" ::)
#define CP_WAIT1 asm volatile("cp.async.wait_group 1;\n" ::)

__device__ __forceinline__ void ldsm4(uint32_t addr, uint32_t* r) {
    asm volatile("ldmatrix.sync.aligned.m8n8.x4.shared.b16 {%0,%1,%2,%3}, [%4];\n"
                 : "=r"(r[0]), "=r"(r[1]), "=r"(r[2]), "=r"(r[3])
                 : "r"(addr));
}

__device__ __forceinline__ void ldsm4t(uint32_t addr, uint32_t* r) {
    asm volatile("ldmatrix.sync.aligned.m8n8.x4.trans.shared.b16 {%0,%1,%2,%3}, [%4];\n"
                 : "=r"(r[0]), "=r"(r[1]), "=r"(r[2]), "=r"(r[3])
                 : "r"(addr));
}

__device__ __forceinline__ void mma_bf16(float* c, const uint32_t* a, const uint32_t* b) {
    asm volatile(
        "mma.sync.aligned.m16n8k16.row.col.f32.bf16.bf16.f32 "
        "{%0,%1,%2,%3}, {%4,%5,%6,%7}, {%8,%9}, {%0,%1,%2,%3};\n"
        : "+f"(c[0]), "+f"(c[1]), "+f"(c[2]), "+f"(c[3])
        : "r"(a[0]), "r"(a[1]), "r"(a[2]), "r"(a[3]), "r"(b[0]), "r"(b[1]));
}

__device__ __forceinline__ void split2(float v, __nv_bfloat16& h, __nv_bfloat16& l) {
    h = __float2bfloat16(v);
    l = __float2bfloat16(v - __bfloat162float(h));
}

__device__ __forceinline__ uint32_t bpack(__nv_bfloat16 a, __nv_bfloat16 b) {
    __nv_bfloat162 p = __halves2bfloat162(a, b);
    return *reinterpret_cast<uint32_t*>(&p);
}

__device__ __forceinline__ void split_store4(float4 v, __nv_bfloat16* H,
                                             __nv_bfloat16* L) {
    __nv_bfloat16 h0, h1, h2, h3, l0, l1, l2, l3;
    split2(v.x, h0, l0);
    split2(v.y, h1, l1);
    split2(v.z, h2, l2);
    split2(v.w, h3, l3);
    *reinterpret_cast<uint2*>(H) = make_uint2(bpack(h0, h1), bpack(h2, h3));
    *reinterpret_cast<uint2*>(L) = make_uint2(bpack(l0, l1), bpack(l2, l3));
}

// FFMA-only exp (harmless; keeps MUFU free). ~2e-6 rel error.
__device__ __forceinline__ float fast_exp(float x) {
    const float L2E = 1.4426950408889634f;
    float t = __fmaf_rn(x, L2E, 0.0f);
    float z = t + 12582912.0f;
    int n = __float_as_int(z) - 0x4B400000;
    float f = t - (z - 12582912.0f);
    float p = 1.3888949e-3f;
    p = __fmaf_rn(p, f, 9.6181291e-3f);
    p = __fmaf_rn(p, f, 5.5504108e-2f);
    p = __fmaf_rn(p, f, 2.4022650e-1f);
    p = __fmaf_rn(p, f, 6.9314718e-1f);
    p = __fmaf_rn(p, f, 1.0f);
    return __int_as_float(__float_as_int(p) + (n << 23));
}

template <int PITCH, int MT>
__device__ __forceinline__ void ldA(const __nv_bfloat16* P, int arow, int acol,
                                    uint32_t a[][4]) {
#pragma unroll
    for (int mt = 0; mt < MT; mt++)
        ldsm4(smem_u32(P + (arow + mt * 16) * PITCH + acol), a[mt]);
}

template <int PITCH, int NP>
__device__ __forceinline__ void ldB(const __nv_bfloat16* P, int brow, int bcol,
                                    uint32_t b[][2]) {
#pragma unroll
    for (int p = 0; p < NP; p++) {
        uint32_t r[4];
        ldsm4(smem_u32(P + (brow + p * 16) * PITCH + bcol), r);
        b[2 * p][0] = r[0];
        b[2 * p][1] = r[1];
        b[2 * p + 1][0] = r[2];
        b[2 * p + 1][1] = r[3];
    }
}

// A fragments via trans: smem holds A^T as [K][m]
template <int PITCH, int MT>
__device__ __forceinline__ void ldAT(const __nv_bfloat16* P, int kc, int m0,
                                     int lane, uint32_t a[][4]) {
    const int row = kc + (lane & 7) + ((lane >> 4) & 1) * 8;
    const int cb = ((lane >> 3) & 1) * 8;
#pragma unroll
    for (int mt = 0; mt < MT; mt++)
        ldsm4t(smem_u32(P + row * PITCH + m0 + mt * 16 + cb), a[mt]);
}

// B fragments via trans: smem holds B as [K][n]
template <int PITCH, int NP>
__device__ __forceinline__ void ldBT(const __nv_bfloat16* P, int kc, int n0,
                                     int lane, uint32_t b[][2]) {
    const int row = kc + (lane & 7) + ((lane >> 3) & 1) * 8;
    const int cb = ((lane >> 4) & 1) * 8;
#pragma unroll
    for (int p = 0; p < NP; p++) {
        uint32_t r[4];
        ldsm4t(smem_u32(P + row * PITCH + n0 + p * 16 + cb), r);
        b[2 * p][0] = r[0];
        b[2 * p][1] = r[1];
        b[2 * p + 1][0] = r[2];
        b[2 * p + 1][1] = r[3];
    }
}

template <int MT, int NT>
__device__ __forceinline__ void mma_tiles(float (*acc)[NT][4], uint32_t a[][4],
                                          uint32_t b[][2]) {
#pragma unroll
    for (int mt = 0; mt < MT; mt++)
#pragma unroll
        for (int nt = 0; nt < NT; nt++) mma_bf16(acc[mt][nt], a[mt], b[nt]);
}

// ============================================================
// Kernel 0a/0b: one-pass fp32 -> bf16 hi/lo plane converters
// conv_x split in two launches so ncu's launch #5 = softmax(0)
// ============================================================
__global__ __launch_bounds__(256) void convert_x_kernel(const float* __restrict__ x,
                                                        int base4) {
    int idx = base4 + blockIdx.x * 256 + threadIdx.x;  // one float4 each
    float4 v = *(const float4*)(x + (size_t)idx * 4);
    split_store4(v, g_xh + (size_t)idx * 4, g_xl + (size_t)idx * 4);
}

__global__ __launch_bounds__(256) void convert_w_kernel(
    const float* __restrict__ Wq, const float* __restrict__ Wk,
    const float* __restrict__ Wv) {
    const int z = blockIdx.z;
    const float* __restrict__ W = (z == 0) ? Wq : (z == 1) ? Wk : Wv;
    size_t base = (size_t)z * DMODEL * DMODEL;
    int idx = blockIdx.x * 256 + threadIdx.x;
    float4 v = *(const float4*)(W + (size_t)idx * 4);
    split_store4(v, g_wh + base + (size_t)idx * 4, g_wl + base + (size_t)idx * 4);
}

// ============================================================
// Kernel 1: QKV projections. cp.async double-buffered, 128x128,
// BK=32, 256 thr, warp 64x32. B-hi fragments kept live.
// ============================================================
#define P1X 40
#define P1W 136
#define XSTG (128 * P1X)  // 5120 el
#define WSTG (32 * P1W)   // 4352 el
#define QKV_SMEM ((2 * 2 * XSTG + 2 * 2 * WSTG) * 2)  // bytes

__global__ __launch_bounds__(256) void qkv_gemm_kernel() {
    extern __shared__ __align__(16) char dynsm[];
    __nv_bfloat16* Xh = (__nv_bfloat16*)dynsm;       // [2][XSTG]
    __nv_bfloat16* Xl = Xh + 2 * XSTG;
    __nv_bfloat16* Wh2 = Xl + 2 * XSTG;              // [2][WSTG]
    __nv_bfloat16* Wl2 = Wh2 + 2 * WSTG;

    const int z = blockIdx.z;
    const __nv_bfloat16* __restrict__ Wh = g_wh + (size_t)z * DMODEL * DMODEL;
    const __nv_bfloat16* __restrict__ Wl = g_wl + (size_t)z * DMODEL * DMODEL;
    __nv_bfloat16* Ch = (z == 0) ? g_qh : (z == 1) ? g_kh : g_vh;
    __nv_bfloat16* Cl = (z == 0) ? g_ql : (z == 1) ? g_kl : g_vl;
    const float scale = (z == 0) ? 0.125f : 1.0f;

    const int m0 = blockIdx.y * 128;
    const int n0 = blockIdx.x * 128;

    const int t = threadIdx.x, lane = t & 31, w = t >> 5;
    const int wm = (w & 1) * 64, wn = (w >> 1) * 32;

    float acc[4][4][4] = {};
    const int arow = wm + (lane & 15);

    auto issue_stage = [&](int s, int kk) {
#pragma unroll
        for (int i = 0; i < 2; i++) {
            int e = t + i * 256;
            int r = e >> 2, c = (e & 3) * 8;
            cp16(&Xh[s * XSTG + r * P1X + c], g_xh + (size_t)(m0 + r) * DMODEL + kk + c);
            cp16(&Xl[s * XSTG + r * P1X + c], g_xl + (size_t)(m0 + r) * DMODEL + kk + c);
            int r2 = e >> 4, c2 = (e & 15) * 8;
            cp16(&Wh2[s * WSTG + r2 * P1W + c2], Wh + (size_t)(kk + r2) * DMODEL + n0 + c2);
            cp16(&Wl2[s * WSTG + r2 * P1W + c2], Wl + (size_t)(kk + r2) * DMODEL + n0 + c2);
        }
        CP_COMMIT;
    };

    issue_stage(0, 0);
    const int NIT = DMODEL / 32;  // 24
    for (int it = 0; it < NIT; it++) {
        if (it + 1 < NIT) {
            issue_stage((it + 1) & 1, (it + 1) * 32);
            CP_WAIT1;
        } else {
            CP_WAIT0;
        }
        __syncthreads();

        const __nv_bfloat16* xh = Xh + (it & 1) * XSTG;
        const __nv_bfloat16* xl = Xl + (it & 1) * XSTG;
        const __nv_bfloat16* wh2 = Wh2 + (it & 1) * WSTG;
        const __nv_bfloat16* wl2 = Wl2 + (it & 1) * WSTG;
#pragma unroll
        for (int ks = 0; ks < 2; ks++) {
            const int acol = ks * 16 + (lane >> 4) * 8;
            uint32_t a[4][4], bh[4][2], bl[4][2];
            ldA<P1X, 4>(xh, arow, acol, a);
            ldBT<P1W, 2>(wh2, ks * 16, wn, lane, bh);
            mma_tiles<4, 4>(acc, a, bh);
            ldBT<P1W, 2>(wl2, ks * 16, wn, lane, bl);
            mma_tiles<4, 4>(acc, a, bl);
            ldA<P1X, 4>(xl, arow, acol, a);
            mma_tiles<4, 4>(acc, a, bh);
        }
        __syncthreads();
    }

    const int g = lane >> 2, tig = lane & 3;
#pragma unroll
    for (int mt = 0; mt < 4; mt++) {
        int row = m0 + wm + mt * 16 + g;
#pragma unroll
        for (int nt = 0; nt < 4; nt++) {
            int col = n0 + wn + nt * 8 + 2 * tig;
            __nv_bfloat16 h0, l0, h1, l1;
            split2(acc[mt][nt][0] * scale, h0, l0);
            split2(acc[mt][nt][1] * scale, h1, l1);
            *(__nv_bfloat162*)(Ch + (size_t)row * DMODEL + col) = __halves2bfloat162(h0, h1);
            *(__nv_bfloat162*)(Cl + (size_t)row * DMODEL + col) = __halves2bfloat162(l0, l1);
            split2(acc[mt][nt][2] * scale, h0, l0);
            split2(acc[mt][nt][3] * scale, h1, l1);
            *(__nv_bfloat162*)(Ch + (size_t)(row + 8) * DMODEL + col) = __halves2bfloat162(h0, h1);
            *(__nv_bfloat162*)(Cl + (size_t)(row + 8) * DMODEL + col) = __halves2bfloat162(l0, l1);
        }
    }
}

// ============================================================
// Kernel 2: scores for ONE batch. 128x128 tile, K=64 resident.
// 256 thr, 8 warps of 64x32. B-hi kept live.
// ============================================================
#define P2 72

__global__ __launch_bounds__(256) void scores_kernel(int b) {
    extern __shared__ __align__(16) __nv_bfloat16 sm2[];
    __nv_bfloat16* Qh = sm2;
    __nv_bfloat16* Ql = Qh + 128 * P2;
    __nv_bfloat16* Kh2 = Ql + 128 * P2;
    __nv_bfloat16* Kl2 = Kh2 + 128 * P2;

    const int h = blockIdx.z;
    const int i0 = blockIdx.y * 128;
    const int j0 = blockIdx.x * 128;

    const int t = threadIdx.x, lane = t & 31, w = t >> 5;
    const int wm = (w & 1) * 64, wn = (w >> 1) * 32;

    const __nv_bfloat16* qhb = g_qh + (size_t)b * SEQ * DMODEL + h * DHEAD;
    const __nv_bfloat16* qlb = g_ql + (size_t)b * SEQ * DMODEL + h * DHEAD;
    const __nv_bfloat16* khb = g_kh + (size_t)b * SEQ * DMODEL + h * DHEAD;
    const __nv_bfloat16* klb = g_kl + (size_t)b * SEQ * DMODEL + h * DHEAD;

#pragma unroll
    for (int e = t; e < 1024; e += 256) {
        int r = e >> 3, c = (e & 7) * 8;
        *(uint4*)&Qh[r * P2 + c] = *(const uint4*)(qhb + (size_t)(i0 + r) * DMODEL + c);
        *(uint4*)&Ql[r * P2 + c] = *(const uint4*)(qlb + (size_t)(i0 + r) * DMODEL + c);
        *(uint4*)&Kh2[r * P2 + c] = *(const uint4*)(khb + (size_t)(j0 + r) * DMODEL + c);
        *(uint4*)&Kl2[r * P2 + c] = *(const uint4*)(klb + (size_t)(j0 + r) * DMODEL + c);
    }
    __syncthreads();

    float acc[4][4][4] = {};
    const int arow = wm + (lane & 15);
    const int bro = wn + (lane & 7) + (lane >> 4) * 8;

#pragma unroll
    for (int ks = 0; ks < 4; ks++) {
        const int acol = ks * 16 + (lane >> 4) * 8;
        const int bcol = ks * 16 + ((lane >> 3) & 1) * 8;
        uint32_t a[4][4], bh[4][2], bl[4][2];
        ldA<P2, 4>(Qh, arow, acol, a);
        ldB<P2, 2>(Kh2, bro, bcol, bh);
        mma_tiles<4, 4>(acc, a, bh);
        ldB<P2, 2>(Kl2, bro, bcol, bl);
        mma_tiles<4, 4>(acc, a, bl);
        ldA<P2, 4>(Ql, arow, acol, a);
        mma_tiles<4, 4>(acc, a, bh);
    }

    float* Sb = g_attn + (size_t)(b * NHEAD + h) * SEQ * SEQ;
    const int g = lane >> 2, tig = lane & 3;
#pragma unroll
    for (int mt = 0; mt < 4; mt++) {
        int row = i0 + wm + mt * 16 + g;
#pragma unroll
        for (int nt = 0; nt < 4; nt++) {
            int col = j0 + wn + nt * 8 + 2 * tig;
            *(float2*)(Sb + (size_t)row * SEQ + col) =
                make_float2(acc[mt][nt][0], acc[mt][nt][1]);
            *(float2*)(Sb + (size_t)(row + 8) * SEQ + col) =
                make_float2(acc[mt][nt][2], acc[mt][nt][3]);
        }
    }
}

// ============================================================
// Kernel 3: softmax (FFMA exp, no max pass) + theta mix + LN.
// 512 thr, each owns 2 consecutive k (float2) — low reg pressure.
// Parallel warp-tree block reductions.
// ============================================================
#define NW3 16

template <int V>
__device__ __forceinline__ void blockReduceSumV(float v[V], float* red, float* red2) {
    const int lane = threadIdx.x & 31, w = threadIdx.x >> 5;
#pragma unroll
    for (int h = 0; h < V; h++)
#pragma unroll
        for (int o = 16; o; o >>= 1)
            v[h] += __shfl_xor_sync(0xffffffffu, v[h], o);
    if (lane == 0) {
#pragma unroll
        for (int h = 0; h < V; h++) red[h * NW3 + w] = v[h];
    }
    __syncthreads();
    if (w < V / 2) {
        int val = 2 * w + (lane >> 4);
        float s = red[val * NW3 + (lane & 15)];
#pragma unroll
        for (int o = 8; o; o >>= 1) s += __shfl_xor_sync(0xffffffffu, s, o);
        if ((lane & 15) == 0) red2[val] = s;
    }
    __syncthreads();
#pragma unroll
    for (int h = 0; h < V; h++) v[h] = red2[h];
    __syncthreads();
}

__global__ __launch_bounds__(512) void softmax_theta_ln_kernel(
    int b, const float* __restrict__ theta,
    const float* __restrict__ lnS, const float* __restrict__ lnB) {
    __shared__ float th[144];
    __shared__ float red[24 * NW3];
    __shared__ float red2[24];

    const int qi = blockIdx.x;
    const int t = threadIdx.x;  // owns k = 2t, 2t+1

    if (t < 144) th[t] = theta[t];

    float2 r[NHEAD];
#pragma unroll
    for (int h = 0; h < NHEAD; h++) {
        const float* src = g_attn + ((size_t)(b * NHEAD + h) * SEQ + qi) * SEQ;
        r[h] = *(const float2*)(src + 2 * t);
    }
    float2 s2v = *(const float2*)(lnS + 2 * t);
    float2 b2v = *(const float2*)(lnB + 2 * t);
    __syncthreads();

    // softmax without max subtraction; FFMA-pipe exp
    float sum[NHEAD];
#pragma unroll
    for (int h = 0; h < NHEAD; h++) {
        r[h].x = fast_exp(r[h].x);
        r[h].y = fast_exp(r[h].y);
        sum[h] = r[h].x + r[h].y;
    }
    blockReduceSumV<12>(sum, red, red2);
#pragma unroll
    for (int h = 0; h < NHEAD; h++) {
        float inv = 1.0f / sum[h];
        r[h].x *= inv;
        r[h].y *= inv;
    }

    // theta head-mix (in place: overwrite r with mixed values)
    float2 a[NHEAD];
#pragma unroll
    for (int i = 0; i < NHEAD; i++) {
        float ax = 0.f, ay = 0.f;
#pragma unroll
        for (int h = 0; h < NHEAD; h++) {
            float wv = th[h * NHEAD + i];
            ax += wv * r[h].x;
            ay += wv * r[h].y;
        }
        a[i].x = ax;
        a[i].y = ay;
    }

    float st[24];
#pragma unroll
    for (int i = 0; i < NHEAD; i++) {
        st[i] = a[i].x + a[i].y;
        st[12 + i] = a[i].x * a[i].x + a[i].y * a[i].y;
    }
    blockReduceSumV<24>(st, red, red2);

#pragma unroll
    for (int i = 0; i < NHEAD; i++) {
        float mean = st[i] * (1.0f / SEQ);
        float var = st[12 + i] * (1.0f / SEQ) - mean * mean;
        float rstd = rsqrtf(var + 1e-6f);
        size_t off = ((size_t)(b * NHEAD + i) * SEQ + qi) * SEQ + 2 * t;
        float ox = (a[i].x - mean) * rstd * s2v.x + b2v.x;
        float oy = (a[i].y - mean) * rstd * s2v.y + b2v.y;
        __nv_bfloat16 h0, l0, h1, l1;
        split2(ox, h0, l0);
        split2(oy, h1, l1);
        *(__nv_bfloat162*)(g_ah + off) = __halves2bfloat162(h0, h1);
        *(__nv_bfloat162*)(g_al + off) = __halves2bfloat162(l0, l1);
    }
}

// ============================================================
// Kernel 4: out (ALL batches). 128(k) x 64(d), q-chunk 32,
// 128 thr, 4 warps of 64(k)x32(d). cp.async double-buffered.
// ============================================================
#define PA 136
#define PV 72
#define ASTG (32 * PA)  // 4352 el
#define VSTG (32 * PV)  // 2304 el
#define OUT_SMEM ((2 * 2 * ASTG + 2 * 2 * VSTG) * 2)  // bytes

__global__ __launch_bounds__(128) void out_gemm_kernel(float* __restrict__ out) {
    extern __shared__ __align__(16) char dynsm4[];
    __nv_bfloat16* Ahs = (__nv_bfloat16*)dynsm4;  // [2][ASTG]
    __nv_bfloat16* Als = Ahs + 2 * ASTG;
    __nv_bfloat16* Vhs = Als + 2 * ASTG;          // [2][VSTG]
    __nv_bfloat16* Vls = Vhs + 2 * VSTG;

    const int bh = blockIdx.y;
    const int b = bh / NHEAD, h = bh % NHEAD;
    const int k0b = blockIdx.x * 128;

    const int t = threadIdx.x, lane = t & 31, w = t >> 5;
    const int wm = (w & 1) * 64;   // k-dim
    const int wn = (w >> 1) * 32;  // d-dim

    const __nv_bfloat16* ahb = g_ah + (size_t)(b * NHEAD + h) * SEQ * SEQ;
    const __nv_bfloat16* alb = g_al + (size_t)(b * NHEAD + h) * SEQ * SEQ;
    const __nv_bfloat16* vhb = g_vh + (size_t)b * SEQ * DMODEL + h * DHEAD;
    const __nv_bfloat16* vlb = g_vl + (size_t)b * SEQ * DMODEL + h * DHEAD;

    float acc[4][4][4] = {};

    auto issue_stage = [&](int s, int q0) {
#pragma unroll
        for (int i = 0; i < 4; i++) {
            int idx = t + i * 128;
            int r = idx >> 4, c = (idx & 15) * 8;
            cp16(&Ahs[s * ASTG + r * PA + c], ahb + (size_t)(q0 + r) * SEQ + k0b + c);
            cp16(&Als[s * ASTG + r * PA + c], alb + (size_t)(q0 + r) * SEQ + k0b + c);
        }
#pragma unroll
        for (int i = 0; i < 2; i++) {
            int idx = t + i * 128;
            int r = idx >> 3, c = (idx & 7) * 8;
            cp16(&Vhs[s * VSTG + r * PV + c], vhb + (size_t)(q0 + r) * DMODEL + c);
            cp16(&Vls[s * VSTG + r * PV + c], vlb + (size_t)(q0 + r) * DMODEL + c);
        }
        CP_COMMIT;
    };

    issue_stage(0, 0);
    const int NIT = SEQ / 32;  // 32
    for (int it = 0; it < NIT; it++) {
        if (it + 1 < NIT) {
            issue_stage((it + 1) & 1, (it + 1) * 32);
            CP_WAIT1;
        } else {
            CP_WAIT0;
        }
        __syncthreads();

        const __nv_bfloat16* ah = Ahs + (it & 1) * ASTG;
        const __nv_bfloat16* al = Als + (it & 1) * ASTG;
        const __nv_bfloat16* vh = Vhs + (it & 1) * VSTG;
        const __nv_bfloat16* vl = Vls + (it & 1) * VSTG;
#pragma unroll
        for (int ks = 0; ks < 2; ks++) {
            const int qc = ks * 16;
            uint32_t a[4][4], bh2[4][2], bl2[4][2];
            ldAT<PA, 4>(ah, qc, wm, lane, a);
            ldBT<PV, 2>(vh, qc, wn, lane, bh2);
            mma_tiles<4, 4>(acc, a, bh2);
            ldBT<PV, 2>(vl, qc, wn, lane, bl2);
            mma_tiles<4, 4>(acc, a, bl2);
            ldAT<PA, 4>(al, qc, wm, lane, a);
            mma_tiles<4, 4>(acc, a, bh2);
        }
        __syncthreads();
    }

    const int g = lane >> 2, tig = lane & 3;
#pragma unroll
    for (int mt = 0; mt < 4; mt++) {
        int row = k0b + wm + mt * 16 + g;
#pragma unroll
        for (int nt = 0; nt < 4; nt++) {
            int col = h * DHEAD + wn + nt * 8 + 2 * tig;
            *(float2*)(out + (size_t)(b * SEQ + row) * DMODEL + col) =
                make_float2(acc[mt][nt][0], acc[mt][nt][1]);
            *(float2*)(out + (size_t)(b * SEQ + row + 8) * DMODEL + col) =
                make_float2(acc[mt][nt][2], acc[mt][nt][3]);
        }
    }
}

// ============================================================
extern "C" void kernel_launch(void* const* d_in, const int* in_sizes, int n_in,
                              void* d_out, int out_size) {
    const float* x     = (const float*)d_in[0];
    const float* Wq    = (const float*)d_in[1];
    const float* Wk    = (const float*)d_in[2];
    const float* Wv    = (const float*)d_in[3];
    const float* theta = (const float*)d_in[4];
    const float* lnS   = (const float*)d_in[5];
    const float* lnB   = (const float*)d_in[6];
    float* out = (float*)d_out;

    // 0. convert inputs to bf16 hi/lo planes.
    //    conv_x split into 2 launches so ncu's launch #5 = softmax(b=0):
    //    0:convx, 1:convx, 2:convw, 3:qkv, 4:scores(0), 5:softmax(0)
    const int X4 = BN * DMODEL / 4;  // total float4s
    convert_x_kernel<<<X4 / 2 / 256, 256>>>(x, 0);
    convert_x_kernel<<<X4 / 2 / 256, 256>>>(x, X4 / 2);
    {
        dim3 grid(DMODEL * DMODEL / 4 / 256, 1, 3);
        convert_w_kernel<<<grid, 256>>>(Wq, Wk, Wv);
    }
    // 1. QKV projections (cp.async pipelined)
    {
        cudaFuncSetAttribute(qkv_gemm_kernel,
                             cudaFuncAttributeMaxDynamicSharedMemorySize, QKV_SMEM);
        dim3 grid(DMODEL / 128, BN / 128, 3);
        qkv_gemm_kernel<<<grid, 256, QKV_SMEM>>>();
    }
    // 2-3. per-batch scores -> softmax pairs: S (48 MB/batch) stays in L2
    int smem = 4 * 128 * P2 * sizeof(__nv_bfloat16);  // 73728 B
    cudaFuncSetAttribute(scores_kernel,
                         cudaFuncAttributeMaxDynamicSharedMemorySize, smem);
    for (int b = 0; b < BATCH; b++) {
        dim3 grid2(SEQ / 128, SEQ / 128, NHEAD);
        scores_kernel<<<grid2, 256, smem>>>(b);
        softmax_theta_ln_kernel<<<SEQ, 512>>>(b, theta, lnS, lnB);
    }
    // 4. output GEMM, full batch (384 CTAs), cp.async pipelined
    {
        cudaFuncSetAttribute(out_gemm_kernel,
                             cudaFuncAttributeMaxDynamicSharedMemorySize, OUT_SMEM);
        dim3 grid4(SEQ / 128, BATCH * NHEAD);
        out_gemm_kernel<<<grid4, 128, OUT_SMEM>>>(out);
    }
}

// round 12
// speedup vs baseline: 1.0907x; 1.0907x over previous
#include <cuda_runtime.h>
#include <cuda_bf16.h>
#include <math.h>
#include <stdint.h>

#define BATCH 4
#define SEQ 1024
#define DMODEL 768
#define NHEAD 12
#define DHEAD 64
#define BN (BATCH*SEQ)

// ---- scratch (static device globals; no allocation) ----
__device__ float g_attn[(size_t)BATCH * NHEAD * SEQ * SEQ];        // fp32 S
__device__ __nv_bfloat16 g_ah[(size_t)BATCH * NHEAD * SEQ * SEQ];  // A hi
__device__ __nv_bfloat16 g_al[(size_t)BATCH * NHEAD * SEQ * SEQ];  // A lo
__device__ __nv_bfloat16 g_qh[BN * DMODEL], g_ql[BN * DMODEL];
__device__ __nv_bfloat16 g_kh[BN * DMODEL], g_kl[BN * DMODEL];
__device__ __nv_bfloat16 g_vh[BN * DMODEL], g_vl[BN * DMODEL];
__device__ __nv_bfloat16 g_xh[BN * DMODEL], g_xl[BN * DMODEL];
__device__ __nv_bfloat16 g_wh[3 * DMODEL * DMODEL], g_wl[3 * DMODEL * DMODEL];

// ============================================================
// helpers
// ============================================================
__device__ __forceinline__ uint32_t smem_u32(const void* p) {
    return (uint32_t)__cvta_generic_to_shared(p);
}

__device__ __forceinline__ void cp16(void* smem, const void* gmem) {
    asm volatile("cp.async.cg.shared.global [%0], [%1], 16;\n" ::"r"(smem_u32(smem)),
                 "l"(gmem));
}
#define CP_COMMIT asm volatile("cp.async.commit_group;\n" ::)
#define CP_WAIT0 asm volatile("cp.async.wait_group 0;\n" ::)
#define CP_WAIT1 asm volatile("cp.async.wait_group 1;\n" ::)

__device__ __forceinline__ void ldsm4(uint32_t addr, uint32_t* r) {
    asm volatile("ldmatrix.sync.aligned.m8n8.x4.shared.b16 {%0,%1,%2,%3}, [%4];\n"
                 : "=r"(r[0]), "=r"(r[1]), "=r"(r[2]), "=r"(r[3])
                 : "r"(addr));
}

__device__ __forceinline__ void ldsm4t(uint32_t addr, uint32_t* r) {
    asm volatile("ldmatrix.sync.aligned.m8n8.x4.trans.shared.b16 {%0,%1,%2,%3}, [%4];\n"
                 : "=r"(r[0]), "=r"(r[1]), "=r"(r[2]), "=r"(r[3])
                 : "r"(addr));
}

__device__ __forceinline__ void mma_bf16(float* c, const uint32_t* a, const uint32_t* b) {
    asm volatile(
        "mma.sync.aligned.m16n8k16.row.col.f32.bf16.bf16.f32 "
        "{%0,%1,%2,%3}, {%4,%5,%6,%7}, {%8,%9}, {%0,%1,%2,%3};\n"
        : "+f"(c[0]), "+f"(c[1]), "+f"(c[2]), "+f"(c[3])
        : "r"(a[0]), "r"(a[1]), "r"(a[2]), "r"(a[3]), "r"(b[0]), "r"(b[1]));
}

__device__ __forceinline__ void split2(float v, __nv_bfloat16& h, __nv_bfloat16& l) {
    h = __float2bfloat16(v);
    l = __float2bfloat16(v - __bfloat162float(h));
}

__device__ __forceinline__ uint32_t bpack(__nv_bfloat16 a, __nv_bfloat16 b) {
    __nv_bfloat162 p = __halves2bfloat162(a, b);
    return *reinterpret_cast<uint32_t*>(&p);
}

__device__ __forceinline__ void split_store4(float4 v, __nv_bfloat16* H,
                                             __nv_bfloat16* L) {
    __nv_bfloat16 h0, h1, h2, h3, l0, l1, l2, l3;
    split2(v.x, h0, l0);
    split2(v.y, h1, l1);
    split2(v.z, h2, l2);
    split2(v.w, h3, l3);
    *reinterpret_cast<uint2*>(H) = make_uint2(bpack(h0, h1), bpack(h2, h3));
    *reinterpret_cast<uint2*>(L) = make_uint2(bpack(l0, l1), bpack(l2, l3));
}

// FFMA-only exp. ~2e-6 rel error.
__device__ __forceinline__ float fast_exp(float x) {
    const float L2E = 1.4426950408889634f;
    float t = __fmaf_rn(x, L2E, 0.0f);
    float z = t + 12582912.0f;
    int n = __float_as_int(z) - 0x4B400000;
    float f = t - (z - 12582912.0f);
    float p = 1.3888949e-3f;
    p = __fmaf_rn(p, f, 9.6181291e-3f);
    p = __fmaf_rn(p, f, 5.5504108e-2f);
    p = __fmaf_rn(p, f, 2.4022650e-1f);
    p = __fmaf_rn(p, f, 6.9314718e-1f);
    p = __fmaf_rn(p, f, 1.0f);
    return __int_as_float(__float_as_int(p) + (n << 23));
}

template <int PITCH, int MT>
__device__ __forceinline__ void ldA(const __nv_bfloat16* P, int arow, int acol,
                                    uint32_t a[][4]) {
#pragma unroll
    for (int mt = 0; mt < MT; mt++)
        ldsm4(smem_u32(P + (arow + mt * 16) * PITCH + acol), a[mt]);
}

template <int PITCH, int NP>
__device__ __forceinline__ void ldB(const __nv_bfloat16* P, int brow, int bcol,
                                    uint32_t b[][2]) {
#pragma unroll
    for (int p = 0; p < NP; p++) {
        uint32_t r[4];
        ldsm4(smem_u32(P + (brow + p * 16) * PITCH + bcol), r);
        b[2 * p][0] = r[0];
        b[2 * p][1] = r[1];
        b[2 * p + 1][0] = r[2];
        b[2 * p + 1][1] = r[3];
    }
}

// A fragments via trans: smem holds A^T as [K][m]
template <int PITCH, int MT>
__device__ __forceinline__ void ldAT(const __nv_bfloat16* P, int kc, int m0,
                                     int lane, uint32_t a[][4]) {
    const int row = kc + (lane & 7) + ((lane >> 4) & 1) * 8;
    const int cb = ((lane >> 3) & 1) * 8;
#pragma unroll
    for (int mt = 0; mt < MT; mt++)
        ldsm4t(smem_u32(P + row * PITCH + m0 + mt * 16 + cb), a[mt]);
}

// B fragments via trans: smem holds B as [K][n]
template <int PITCH, int NP>
__device__ __forceinline__ void ldBT(const __nv_bfloat16* P, int kc, int n0,
                                     int lane, uint32_t b[][2]) {
    const int row = kc + (lane & 7) + ((lane >> 3) & 1) * 8;
    const int cb = ((lane >> 4) & 1) * 8;
#pragma unroll
    for (int p = 0; p < NP; p++) {
        uint32_t r[4];
        ldsm4t(smem_u32(P + row * PITCH + n0 + p * 16 + cb), r);
        b[2 * p][0] = r[0];
        b[2 * p][1] = r[1];
        b[2 * p + 1][0] = r[2];
        b[2 * p + 1][1] = r[3];
    }
}

template <int MT, int NT>
__device__ __forceinline__ void mma_tiles(float (*acc)[NT][4], uint32_t a[][4],
                                          uint32_t b[][2]) {
#pragma unroll
    for (int mt = 0; mt < MT; mt++)
#pragma unroll
        for (int nt = 0; nt < NT; nt++) mma_bf16(acc[mt][nt], a[mt], b[nt]);
}

// ============================================================
// Kernel 0a/0b: one-pass fp32 -> bf16 hi/lo plane converters
// conv_x split in two launches so ncu's launch #5 = softmax(0)
// ============================================================
__global__ __launch_bounds__(256) void convert_x_kernel(const float* __restrict__ x,
                                                        int base4) {
    int idx = base4 + blockIdx.x * 256 + threadIdx.x;
    float4 v = *(const float4*)(x + (size_t)idx * 4);
    split_store4(v, g_xh + (size_t)idx * 4, g_xl + (size_t)idx * 4);
}

__global__ __launch_bounds__(256) void convert_w_kernel(
    const float* __restrict__ Wq, const float* __restrict__ Wk,
    const float* __restrict__ Wv) {
    const int z = blockIdx.z;
    const float* __restrict__ W = (z == 0) ? Wq : (z == 1) ? Wk : Wv;
    size_t base = (size_t)z * DMODEL * DMODEL;
    int idx = blockIdx.x * 256 + threadIdx.x;
    float4 v = *(const float4*)(W + (size_t)idx * 4);
    split_store4(v, g_wh + base + (size_t)idx * 4, g_wl + base + (size_t)idx * 4);
}

// ============================================================
// Kernel 1: QKV projections. CTA 128(m) x 256(n), BK=32,
// 8 warps of 64x64, cp.async double-buffered. 6 MMA/LDSM.
// ============================================================
#define P1X 40
#define P1W2 264
#define XSTG (128 * P1X)   // 5120 el
#define WSTG2 (32 * P1W2)  // 8448 el
#define QKV_SMEM ((2 * 2 * XSTG + 2 * 2 * WSTG2) * 2)  // 108544 B

__global__ __launch_bounds__(256) void qkv_gemm_kernel() {
    extern __shared__ __align__(16) char dynsm[];
    __nv_bfloat16* Xh = (__nv_bfloat16*)dynsm;   // [2][XSTG]
    __nv_bfloat16* Xl = Xh + 2 * XSTG;
    __nv_bfloat16* Wh2 = Xl + 2 * XSTG;          // [2][WSTG2]
    __nv_bfloat16* Wl2 = Wh2 + 2 * WSTG2;

    const int z = blockIdx.z;
    const __nv_bfloat16* __restrict__ Wh = g_wh + (size_t)z * DMODEL * DMODEL;
    const __nv_bfloat16* __restrict__ Wl = g_wl + (size_t)z * DMODEL * DMODEL;
    __nv_bfloat16* Ch = (z == 0) ? g_qh : (z == 1) ? g_kh : g_vh;
    __nv_bfloat16* Cl = (z == 0) ? g_ql : (z == 1) ? g_kl : g_vl;
    const float scale = (z == 0) ? 0.125f : 1.0f;

    const int m0 = blockIdx.y * 128;
    const int n0 = blockIdx.x * 256;

    const int t = threadIdx.x, lane = t & 31, w = t >> 5;
    const int wm = (w & 1) * 64;   // m: 2 x 64
    const int wn = (w >> 1) * 64;  // n: 4 x 64

    float acc[4][8][4] = {};
    const int arow = wm + (lane & 15);

    auto issue_stage = [&](int s, int kk) {
        // X tile [128 m][32 k]: 512 uint4 per plane
#pragma unroll
        for (int i = 0; i < 2; i++) {
            int e = t + i * 256;
            int r = e >> 2, c = (e & 3) * 8;
            cp16(&Xh[s * XSTG + r * P1X + c], g_xh + (size_t)(m0 + r) * DMODEL + kk + c);
            cp16(&Xl[s * XSTG + r * P1X + c], g_xl + (size_t)(m0 + r) * DMODEL + kk + c);
        }
        // W tile [32 k][256 n]: 1024 uint4 per plane
#pragma unroll
        for (int i = 0; i < 4; i++) {
            int e = t + i * 256;
            int r = e >> 5, c = (e & 31) * 8;
            cp16(&Wh2[s * WSTG2 + r * P1W2 + c], Wh + (size_t)(kk + r) * DMODEL + n0 + c);
            cp16(&Wl2[s * WSTG2 + r * P1W2 + c], Wl + (size_t)(kk + r) * DMODEL + n0 + c);
        }
        CP_COMMIT;
    };

    issue_stage(0, 0);
    const int NIT = DMODEL / 32;  // 24
    for (int it = 0; it < NIT; it++) {
        if (it + 1 < NIT) {
            issue_stage((it + 1) & 1, (it + 1) * 32);
            CP_WAIT1;
        } else {
            CP_WAIT0;
        }
        __syncthreads();

        const __nv_bfloat16* xh = Xh + (it & 1) * XSTG;
        const __nv_bfloat16* xl = Xl + (it & 1) * XSTG;
        const __nv_bfloat16* wh2 = Wh2 + (it & 1) * WSTG2;
        const __nv_bfloat16* wl2 = Wl2 + (it & 1) * WSTG2;
#pragma unroll
        for (int ks = 0; ks < 2; ks++) {
            const int acol = ks * 16 + (lane >> 4) * 8;
            uint32_t a[4][4], bh[8][2], bl[8][2];
            ldA<P1X, 4>(xh, arow, acol, a);
            ldBT<P1W2, 4>(wh2, ks * 16, wn, lane, bh);
            mma_tiles<4, 8>(acc, a, bh);
            ldBT<P1W2, 4>(wl2, ks * 16, wn, lane, bl);
            mma_tiles<4, 8>(acc, a, bl);
            ldA<P1X, 4>(xl, arow, acol, a);
            mma_tiles<4, 8>(acc, a, bh);
        }
        __syncthreads();
    }

    const int g = lane >> 2, tig = lane & 3;
#pragma unroll
    for (int mt = 0; mt < 4; mt++) {
        int row = m0 + wm + mt * 16 + g;
#pragma unroll
        for (int nt = 0; nt < 8; nt++) {
            int col = n0 + wn + nt * 8 + 2 * tig;
            __nv_bfloat16 h0, l0, h1, l1;
            split2(acc[mt][nt][0] * scale, h0, l0);
            split2(acc[mt][nt][1] * scale, h1, l1);
            *(__nv_bfloat162*)(Ch + (size_t)row * DMODEL + col) = __halves2bfloat162(h0, h1);
            *(__nv_bfloat162*)(Cl + (size_t)row * DMODEL + col) = __halves2bfloat162(l0, l1);
            split2(acc[mt][nt][2] * scale, h0, l0);
            split2(acc[mt][nt][3] * scale, h1, l1);
            *(__nv_bfloat162*)(Ch + (size_t)(row + 8) * DMODEL + col) = __halves2bfloat162(h0, h1);
            *(__nv_bfloat162*)(Cl + (size_t)(row + 8) * DMODEL + col) = __halves2bfloat162(l0, l1);
        }
    }
}

// ============================================================
// Kernel 2: scores for ONE batch. 128x128 tile, K=64 resident.
// 256 thr, 8 warps of 64x32. B-hi kept live.
// ============================================================
#define P2 72

__global__ __launch_bounds__(256) void scores_kernel(int b) {
    extern __shared__ __align__(16) __nv_bfloat16 sm2[];
    __nv_bfloat16* Qh = sm2;
    __nv_bfloat16* Ql = Qh + 128 * P2;
    __nv_bfloat16* Kh2 = Ql + 128 * P2;
    __nv_bfloat16* Kl2 = Kh2 + 128 * P2;

    const int h = blockIdx.z;
    const int i0 = blockIdx.y * 128;
    const int j0 = blockIdx.x * 128;

    const int t = threadIdx.x, lane = t & 31, w = t >> 5;
    const int wm = (w & 1) * 64, wn = (w >> 1) * 32;

    const __nv_bfloat16* qhb = g_qh + (size_t)b * SEQ * DMODEL + h * DHEAD;
    const __nv_bfloat16* qlb = g_ql + (size_t)b * SEQ * DMODEL + h * DHEAD;
    const __nv_bfloat16* khb = g_kh + (size_t)b * SEQ * DMODEL + h * DHEAD;
    const __nv_bfloat16* klb = g_kl + (size_t)b * SEQ * DMODEL + h * DHEAD;

#pragma unroll
    for (int e = t; e < 1024; e += 256) {
        int r = e >> 3, c = (e & 7) * 8;
        *(uint4*)&Qh[r * P2 + c] = *(const uint4*)(qhb + (size_t)(i0 + r) * DMODEL + c);
        *(uint4*)&Ql[r * P2 + c] = *(const uint4*)(qlb + (size_t)(i0 + r) * DMODEL + c);
        *(uint4*)&Kh2[r * P2 + c] = *(const uint4*)(khb + (size_t)(j0 + r) * DMODEL + c);
        *(uint4*)&Kl2[r * P2 + c] = *(const uint4*)(klb + (size_t)(j0 + r) * DMODEL + c);
    }
    __syncthreads();

    float acc[4][4][4] = {};
    const int arow = wm + (lane & 15);
    const int bro = wn + (lane & 7) + (lane >> 4) * 8;

#pragma unroll
    for (int ks = 0; ks < 4; ks++) {
        const int acol = ks * 16 + (lane >> 4) * 8;
        const int bcol = ks * 16 + ((lane >> 3) & 1) * 8;
        uint32_t a[4][4], bh[4][2], bl[4][2];
        ldA<P2, 4>(Qh, arow, acol, a);
        ldB<P2, 2>(Kh2, bro, bcol, bh);
        mma_tiles<4, 4>(acc, a, bh);
        ldB<P2, 2>(Kl2, bro, bcol, bl);
        mma_tiles<4, 4>(acc, a, bl);
        ldA<P2, 4>(Ql, arow, acol, a);
        mma_tiles<4, 4>(acc, a, bh);
    }

    float* Sb = g_attn + (size_t)(b * NHEAD + h) * SEQ * SEQ;
    const int g = lane >> 2, tig = lane & 3;
#pragma unroll
    for (int mt = 0; mt < 4; mt++) {
        int row = i0 + wm + mt * 16 + g;
#pragma unroll
        for (int nt = 0; nt < 4; nt++) {
            int col = j0 + wn + nt * 8 + 2 * tig;
            *(float2*)(Sb + (size_t)row * SEQ + col) =
                make_float2(acc[mt][nt][0], acc[mt][nt][1]);
            *(float2*)(Sb + (size_t)(row + 8) * SEQ + col) =
                make_float2(acc[mt][nt][2], acc[mt][nt][3]);
        }
    }
}

// ============================================================
// Kernel 3: softmax (FFMA exp, no max pass) + theta mix + LN.
// 256 thr, each owns 4 consecutive k. float4 I/O. (R10 version)
// ============================================================
#define NW3 8

template <int V>
__device__ __forceinline__ void blockReduceSumV(float v[V], float* red, float* red2) {
    const int lane = threadIdx.x & 31, w = threadIdx.x >> 5;
#pragma unroll
    for (int h = 0; h < V; h++)
#pragma unroll
        for (int o = 16; o; o >>= 1)
            v[h] += __shfl_xor_sync(0xffffffffu, v[h], o);
    if (lane == 0) {
#pragma unroll
        for (int h = 0; h < V; h++) red[h * NW3 + w] = v[h];
    }
    __syncthreads();
    if (w < V / 4) {
        int val = 4 * w + (lane >> 3);
        float s = red[val * NW3 + (lane & 7)];
#pragma unroll
        for (int o = 4; o; o >>= 1) s += __shfl_xor_sync(0xffffffffu, s, o);
        if ((lane & 7) == 0) red2[val] = s;
    }
    __syncthreads();
#pragma unroll
    for (int h = 0; h < V; h++) v[h] = red2[h];
    __syncthreads();
}

__global__ __launch_bounds__(256) void softmax_theta_ln_kernel(
    int b, const float* __restrict__ theta,
    const float* __restrict__ lnS, const float* __restrict__ lnB) {
    __shared__ float th[144];
    __shared__ float red[24 * NW3];
    __shared__ float red2[24];

    const int qi = blockIdx.x;
    const int t = threadIdx.x;  // owns k = 4t .. 4t+3

    if (t < 144) th[t] = theta[t];

    float4 r[NHEAD];
#pragma unroll
    for (int h = 0; h < NHEAD; h++) {
        const float* src = g_attn + ((size_t)(b * NHEAD + h) * SEQ + qi) * SEQ;
        r[h] = *(const float4*)(src + 4 * t);
    }
    float4 s4 = *(const float4*)(lnS + 4 * t);
    float4 b4 = *(const float4*)(lnB + 4 * t);
    __syncthreads();

    float sum[NHEAD];
#pragma unroll
    for (int h = 0; h < NHEAD; h++) {
        r[h].x = fast_exp(r[h].x);
        r[h].y = fast_exp(r[h].y);
        r[h].z = fast_exp(r[h].z);
        r[h].w = fast_exp(r[h].w);
        sum[h] = (r[h].x + r[h].y) + (r[h].z + r[h].w);
    }
    blockReduceSumV<12>(sum, red, red2);
#pragma unroll
    for (int h = 0; h < NHEAD; h++) {
        float inv = 1.0f / sum[h];
        r[h].x *= inv;
        r[h].y *= inv;
        r[h].z *= inv;
        r[h].w *= inv;
    }

    float4 a[NHEAD];
#pragma unroll
    for (int i = 0; i < NHEAD; i++) {
        float ax = 0.f, ay = 0.f, az = 0.f, aw = 0.f;
#pragma unroll
        for (int h = 0; h < NHEAD; h++) {
            float wv = th[h * NHEAD + i];
            ax += wv * r[h].x;
            ay += wv * r[h].y;
            az += wv * r[h].z;
            aw += wv * r[h].w;
        }
        a[i] = make_float4(ax, ay, az, aw);
    }

    float st[24];
#pragma unroll
    for (int i = 0; i < NHEAD; i++) {
        st[i] = (a[i].x + a[i].y) + (a[i].z + a[i].w);
        st[12 + i] = (a[i].x * a[i].x + a[i].y * a[i].y) +
                     (a[i].z * a[i].z + a[i].w * a[i].w);
    }
    blockReduceSumV<24>(st, red, red2);

#pragma unroll
    for (int i = 0; i < NHEAD; i++) {
        float mean = st[i] * (1.0f / SEQ);
        float var = st[12 + i] * (1.0f / SEQ) - mean * mean;
        float rstd = rsqrtf(var + 1e-6f);
        size_t off = ((size_t)(b * NHEAD + i) * SEQ + qi) * SEQ + 4 * t;
        float4 o;
        o.x = (a[i].x - mean) * rstd * s4.x + b4.x;
        o.y = (a[i].y - mean) * rstd * s4.y + b4.y;
        o.z = (a[i].z - mean) * rstd * s4.z + b4.z;
        o.w = (a[i].w - mean) * rstd * s4.w + b4.w;
        split_store4(o, g_ah + off, g_al + off);
    }
}

// ============================================================
// Kernel 4: out (ALL batches). 128(k) x 64(d), q-chunk 32,
// 128 thr, 4 warps of 64(k)x32(d). cp.async double-buffered.
// ============================================================
#define PA 136
#define PV 72
#define ASTG (32 * PA)  // 4352 el
#define VSTG (32 * PV)  // 2304 el
#define OUT_SMEM ((2 * 2 * ASTG + 2 * 2 * VSTG) * 2)  // bytes

__global__ __launch_bounds__(128) void out_gemm_kernel(float* __restrict__ out) {
    extern __shared__ __align__(16) char dynsm4[];
    __nv_bfloat16* Ahs = (__nv_bfloat16*)dynsm4;  // [2][ASTG]
    __nv_bfloat16* Als = Ahs + 2 * ASTG;
    __nv_bfloat16* Vhs = Als + 2 * ASTG;          // [2][VSTG]
    __nv_bfloat16* Vls = Vhs + 2 * VSTG;

    const int bh = blockIdx.y;
    const int b = bh / NHEAD, h = bh % NHEAD;
    const int k0b = blockIdx.x * 128;

    const int t = threadIdx.x, lane = t & 31, w = t >> 5;
    const int wm = (w & 1) * 64;   // k-dim
    const int wn = (w >> 1) * 32;  // d-dim

    const __nv_bfloat16* ahb = g_ah + (size_t)(b * NHEAD + h) * SEQ * SEQ;
    const __nv_bfloat16* alb = g_al + (size_t)(b * NHEAD + h) * SEQ * SEQ;
    const __nv_bfloat16* vhb = g_vh + (size_t)b * SEQ * DMODEL + h * DHEAD;
    const __nv_bfloat16* vlb = g_vl + (size_t)b * SEQ * DMODEL + h * DHEAD;

    float acc[4][4][4] = {};

    auto issue_stage = [&](int s, int q0) {
#pragma unroll
        for (int i = 0; i < 4; i++) {
            int idx = t + i * 128;
            int r = idx >> 4, c = (idx & 15) * 8;
            cp16(&Ahs[s * ASTG + r * PA + c], ahb + (size_t)(q0 + r) * SEQ + k0b + c);
            cp16(&Als[s * ASTG + r * PA + c], alb + (size_t)(q0 + r) * SEQ + k0b + c);
        }
#pragma unroll
        for (int i = 0; i < 2; i++) {
            int idx = t + i * 128;
            int r = idx >> 3, c = (idx & 7) * 8;
            cp16(&Vhs[s * VSTG + r * PV + c], vhb + (size_t)(q0 + r) * DMODEL + c);
            cp16(&Vls[s * VSTG + r * PV + c], vlb + (size_t)(q0 + r) * DMODEL + c);
        }
        CP_COMMIT;
    };

    issue_stage(0, 0);
    const int NIT = SEQ / 32;  // 32
    for (int it = 0; it < NIT; it++) {
        if (it + 1 < NIT) {
            issue_stage((it + 1) & 1, (it + 1) * 32);
            CP_WAIT1;
        } else {
            CP_WAIT0;
        }
        __syncthreads();

        const __nv_bfloat16* ah = Ahs + (it & 1) * ASTG;
        const __nv_bfloat16* al = Als + (it & 1) * ASTG;
        const __nv_bfloat16* vh = Vhs + (it & 1) * VSTG;
        const __nv_bfloat16* vl = Vls + (it & 1) * VSTG;
#pragma unroll
        for (int ks = 0; ks < 2; ks++) {
            const int qc = ks * 16;
            uint32_t a[4][4], bh2[4][2], bl2[4][2];
            ldAT<PA, 4>(ah, qc, wm, lane, a);
            ldBT<PV, 2>(vh, qc, wn, lane, bh2);
            mma_tiles<4, 4>(acc, a, bh2);
            ldBT<PV, 2>(vl, qc, wn, lane, bl2);
            mma_tiles<4, 4>(acc, a, bl2);
            ldAT<PA, 4>(al, qc, wm, lane, a);
            mma_tiles<4, 4>(acc, a, bh2);
        }
        __syncthreads();
    }

    const int g = lane >> 2, tig = lane & 3;
#pragma unroll
    for (int mt = 0; mt < 4; mt++) {
        int row = k0b + wm + mt * 16 + g;
#pragma unroll
        for (int nt = 0; nt < 4; nt++) {
            int col = h * DHEAD + wn + nt * 8 + 2 * tig;
            *(float2*)(out + (size_t)(b * SEQ + row) * DMODEL + col) =
                make_float2(acc[mt][nt][0], acc[mt][nt][1]);
            *(float2*)(out + (size_t)(b * SEQ + row + 8) * DMODEL + col) =
                make_float2(acc[mt][nt][2], acc[mt][nt][3]);
        }
    }
}

// ============================================================
extern "C" void kernel_launch(void* const* d_in, const int* in_sizes, int n_in,
                              void* d_out, int out_size) {
    const float* x     = (const float*)d_in[0];
    const float* Wq    = (const float*)d_in[1];
    const float* Wk    = (const float*)d_in[2];
    const float* Wv    = (const float*)d_in[3];
    const float* theta = (const float*)d_in[4];
    const float* lnS   = (const float*)d_in[5];
    const float* lnB   = (const float*)d_in[6];
    float* out = (float*)d_out;

    // 0. convert inputs to bf16 hi/lo planes.
    //    launch order: 0:convx 1:convx 2:convw 3:qkv 4:scores(0) 5:softmax(0)
    const int X4 = BN * DMODEL / 4;
    convert_x_kernel<<<X4 / 2 / 256, 256>>>(x, 0);
    convert_x_kernel<<<X4 / 2 / 256, 256>>>(x, X4 / 2);
    {
        dim3 grid(DMODEL * DMODEL / 4 / 256, 1, 3);
        convert_w_kernel<<<grid, 256>>>(Wq, Wk, Wv);
    }
    // 1. QKV projections (128x256 CTA, 64x64 warps, cp.async)
    {
        cudaFuncSetAttribute(qkv_gemm_kernel,
                             cudaFuncAttributeMaxDynamicSharedMemorySize, QKV_SMEM);
        dim3 grid(DMODEL / 256, BN / 128, 3);
        qkv_gemm_kernel<<<grid, 256, QKV_SMEM>>>();
    }
    // 2-3. per-batch scores -> softmax pairs: S (48 MB/batch) stays in L2
    int smem = 4 * 128 * P2 * sizeof(__nv_bfloat16);  // 73728 B
    cudaFuncSetAttribute(scores_kernel,
                         cudaFuncAttributeMaxDynamicSharedMemorySize, smem);
    for (int b = 0; b < BATCH; b++) {
        dim3 grid2(SEQ / 128, SEQ / 128, NHEAD);
        scores_kernel<<<grid2, 256, smem>>>(b);
        softmax_theta_ln_kernel<<<SEQ, 256>>>(b, theta, lnS, lnB);
    }
    // 4. output GEMM, full batch (384 CTAs), cp.async pipelined
    {
        cudaFuncSetAttribute(out_gemm_kernel,
                             cudaFuncAttributeMaxDynamicSharedMemorySize, OUT_SMEM);
        dim3 grid4(SEQ / 128, BATCH * NHEAD);
        out_gemm_kernel<<<grid4, 128, OUT_SMEM>>>(out);
    }
}

// round 14
// speedup vs baseline: 1.1202x; 1.0270x over previous
#include <cuda_runtime.h>
#include <cuda_bf16.h>
#include <math.h>
#include <stdint.h>

#define BATCH 4
#define SEQ 1024
#define DMODEL 768
#define NHEAD 12
#define DHEAD 64
#define BN (BATCH*SEQ)

// ---- scratch (static device globals; no allocation) ----
__device__ float g_attn[(size_t)BATCH * NHEAD * SEQ * SEQ];        // fp32 S
__device__ __nv_bfloat16 g_ah[(size_t)BATCH * NHEAD * SEQ * SEQ];  // A hi
__device__ __nv_bfloat16 g_al[(size_t)BATCH * NHEAD * SEQ * SEQ];  // A lo
__device__ __nv_bfloat16 g_qh[BN * DMODEL], g_ql[BN * DMODEL];
__device__ __nv_bfloat16 g_kh[BN * DMODEL], g_kl[BN * DMODEL];
__device__ __nv_bfloat16 g_vh[BN * DMODEL], g_vl[BN * DMODEL];
__device__ __nv_bfloat16 g_xh[BN * DMODEL], g_xl[BN * DMODEL];
__device__ __nv_bfloat16 g_wh[3 * DMODEL * DMODEL], g_wl[3 * DMODEL * DMODEL];

// ============================================================
// helpers
// ============================================================
__device__ __forceinline__ uint32_t smem_u32(const void* p) {
    return (uint32_t)__cvta_generic_to_shared(p);
}

__device__ __forceinline__ void cp16(void* smem, const void* gmem) {
    asm volatile("cp.async.cg.shared.global [%0], [%1], 16;\n" ::"r"(smem_u32(smem)),
                 "l"(gmem));
}
#define CP_COMMIT asm volatile("cp.async.commit_group;\n" ::)
#define CP_WAIT0 asm volatile("cp.async.wait_group 0;\n" ::)
#define CP_WAIT1 asm volatile("cp.async.wait_group 1;\n" ::)

__device__ __forceinline__ void ldsm4(uint32_t addr, uint32_t* r) {
    asm volatile("ldmatrix.sync.aligned.m8n8.x4.shared.b16 {%0,%1,%2,%3}, [%4];\n"
                 : "=r"(r[0]), "=r"(r[1]), "=r"(r[2]), "=r"(r[3])
                 : "r"(addr));
}

__device__ __forceinline__ void ldsm4t(uint32_t addr, uint32_t* r) {
    asm volatile("ldmatrix.sync.aligned.m8n8.x4.trans.shared.b16 {%0,%1,%2,%3}, [%4];\n"
                 : "=r"(r[0]), "=r"(r[1]), "=r"(r[2]), "=r"(r[3])
                 : "r"(addr));
}

__device__ __forceinline__ void mma_bf16(float* c, const uint32_t* a, const uint32_t* b) {
    asm volatile(
        "mma.sync.aligned.m16n8k16.row.col.f32.bf16.bf16.f32 "
        "{%0,%1,%2,%3}, {%4,%5,%6,%7}, {%8,%9}, {%0,%1,%2,%3};\n"
        : "+f"(c[0]), "+f"(c[1]), "+f"(c[2]), "+f"(c[3])
        : "r"(a[0]), "r"(a[1]), "r"(a[2]), "r"(a[3]), "r"(b[0]), "r"(b[1]));
}

__device__ __forceinline__ void split2(float v, __nv_bfloat16& h, __nv_bfloat16& l) {
    h = __float2bfloat16(v);
    l = __float2bfloat16(v - __bfloat162float(h));
}

__device__ __forceinline__ uint32_t bpack(__nv_bfloat16 a, __nv_bfloat16 b) {
    __nv_bfloat162 p = __halves2bfloat162(a, b);
    return *reinterpret_cast<uint32_t*>(&p);
}

__device__ __forceinline__ void split_store4(float4 v, __nv_bfloat16* H,
                                             __nv_bfloat16* L) {
    __nv_bfloat16 h0, h1, h2, h3, l0, l1, l2, l3;
    split2(v.x, h0, l0);
    split2(v.y, h1, l1);
    split2(v.z, h2, l2);
    split2(v.w, h3, l3);
    *reinterpret_cast<uint2*>(H) = make_uint2(bpack(h0, h1), bpack(h2, h3));
    *reinterpret_cast<uint2*>(L) = make_uint2(bpack(l0, l1), bpack(l2, l3));
}

// FFMA-only exp. ~2e-6 rel error.
__device__ __forceinline__ float fast_exp(float x) {
    const float L2E = 1.4426950408889634f;
    float t = __fmaf_rn(x, L2E, 0.0f);
    float z = t + 12582912.0f;
    int n = __float_as_int(z) - 0x4B400000;
    float f = t - (z - 12582912.0f);
    float p = 1.3888949e-3f;
    p = __fmaf_rn(p, f, 9.6181291e-3f);
    p = __fmaf_rn(p, f, 5.5504108e-2f);
    p = __fmaf_rn(p, f, 2.4022650e-1f);
    p = __fmaf_rn(p, f, 6.9314718e-1f);
    p = __fmaf_rn(p, f, 1.0f);
    return __int_as_float(__float_as_int(p) + (n << 23));
}

template <int PITCH, int MT>
__device__ __forceinline__ void ldA(const __nv_bfloat16* P, int arow, int acol,
                                    uint32_t a[][4]) {
#pragma unroll
    for (int mt = 0; mt < MT; mt++)
        ldsm4(smem_u32(P + (arow + mt * 16) * PITCH + acol), a[mt]);
}

template <int PITCH, int NP>
__device__ __forceinline__ void ldB(const __nv_bfloat16* P, int brow, int bcol,
                                    uint32_t b[][2]) {
#pragma unroll
    for (int p = 0; p < NP; p++) {
        uint32_t r[4];
        ldsm4(smem_u32(P + (brow + p * 16) * PITCH + bcol), r);
        b[2 * p][0] = r[0];
        b[2 * p][1] = r[1];
        b[2 * p + 1][0] = r[2];
        b[2 * p + 1][1] = r[3];
    }
}

// A fragments via trans: smem holds A^T as [K][m]
template <int PITCH, int MT>
__device__ __forceinline__ void ldAT(const __nv_bfloat16* P, int kc, int m0,
                                     int lane, uint32_t a[][4]) {
    const int row = kc + (lane & 7) + ((lane >> 4) & 1) * 8;
    const int cb = ((lane >> 3) & 1) * 8;
#pragma unroll
    for (int mt = 0; mt < MT; mt++)
        ldsm4t(smem_u32(P + row * PITCH + m0 + mt * 16 + cb), a[mt]);
}

// B fragments via trans: smem holds B as [K][n]
template <int PITCH, int NP>
__device__ __forceinline__ void ldBT(const __nv_bfloat16* P, int kc, int n0,
                                     int lane, uint32_t b[][2]) {
    const int row = kc + (lane & 7) + ((lane >> 3) & 1) * 8;
    const int cb = ((lane >> 4) & 1) * 8;
#pragma unroll
    for (int p = 0; p < NP; p++) {
        uint32_t r[4];
        ldsm4t(smem_u32(P + row * PITCH + n0 + p * 16 + cb), r);
        b[2 * p][0] = r[0];
        b[2 * p][1] = r[1];
        b[2 * p + 1][0] = r[2];
        b[2 * p + 1][1] = r[3];
    }
}

template <int MT, int NT>
__device__ __forceinline__ void mma_tiles(float (*acc)[NT][4], uint32_t a[][4],
                                          uint32_t b[][2]) {
#pragma unroll
    for (int mt = 0; mt < MT; mt++)
#pragma unroll
        for (int nt = 0; nt < NT; nt++) mma_bf16(acc[mt][nt], a[mt], b[nt]);
}

// ============================================================
// Kernel 0a/0b: one-pass fp32 -> bf16 hi/lo plane converters
// ============================================================
__global__ __launch_bounds__(256) void convert_x_kernel(const float* __restrict__ x,
                                                        int base4) {
    int idx = base4 + blockIdx.x * 256 + threadIdx.x;
    float4 v = *(const float4*)(x + (size_t)idx * 4);
    split_store4(v, g_xh + (size_t)idx * 4, g_xl + (size_t)idx * 4);
}

__global__ __launch_bounds__(256) void convert_w_kernel(
    const float* __restrict__ Wq, const float* __restrict__ Wk,
    const float* __restrict__ Wv) {
    const int z = blockIdx.z;
    const float* __restrict__ W = (z == 0) ? Wq : (z == 1) ? Wk : Wv;
    size_t base = (size_t)z * DMODEL * DMODEL;
    int idx = blockIdx.x * 256 + threadIdx.x;
    float4 v = *(const float4*)(W + (size_t)idx * 4);
    split_store4(v, g_wh + base + (size_t)idx * 4, g_wl + base + (size_t)idx * 4);
}

// ============================================================
// Kernel 1: QKV projections. CTA 128(m) x 128(n), BK=32,
// 4 warps of 64x64, 128 thr, cp.async double-buffered,
// 2 CTAs/SM for barrier overlap.
// ============================================================
#define P1X 40
#define P1W 136
#define XSTG (128 * P1X)  // 5120 el
#define WSTG (32 * P1W)   // 4352 el
#define QKV_SMEM ((2 * 2 * XSTG + 2 * 2 * WSTG) * 2)  // 75776 B

__global__ __launch_bounds__(128, 2) void qkv_gemm_kernel() {
    extern __shared__ __align__(16) char dynsm[];
    __nv_bfloat16* Xh = (__nv_bfloat16*)dynsm;   // [2][XSTG]
    __nv_bfloat16* Xl = Xh + 2 * XSTG;
    __nv_bfloat16* Wh2 = Xl + 2 * XSTG;          // [2][WSTG]
    __nv_bfloat16* Wl2 = Wh2 + 2 * WSTG;

    const int z = blockIdx.z;
    const __nv_bfloat16* __restrict__ Wh = g_wh + (size_t)z * DMODEL * DMODEL;
    const __nv_bfloat16* __restrict__ Wl = g_wl + (size_t)z * DMODEL * DMODEL;
    __nv_bfloat16* Ch = (z == 0) ? g_qh : (z == 1) ? g_kh : g_vh;
    __nv_bfloat16* Cl = (z == 0) ? g_ql : (z == 1) ? g_kl : g_vl;
    const float scale = (z == 0) ? 0.125f : 1.0f;

    const int m0 = blockIdx.y * 128;
    const int n0 = blockIdx.x * 128;

    const int t = threadIdx.x, lane = t & 31, w = t >> 5;
    const int wm = (w & 1) * 64;   // m: 2 x 64
    const int wn = (w >> 1) * 64;  // n: 2 x 64

    float acc[4][8][4] = {};
    const int arow = wm + (lane & 15);

    auto issue_stage = [&](int s, int kk) {
        // X tile [128 m][32 k]: 512 uint4 per plane, 128 thr -> 4 each
#pragma unroll
        for (int i = 0; i < 4; i++) {
            int e = t + i * 128;
            int r = e >> 2, c = (e & 3) * 8;
            cp16(&Xh[s * XSTG + r * P1X + c], g_xh + (size_t)(m0 + r) * DMODEL + kk + c);
            cp16(&Xl[s * XSTG + r * P1X + c], g_xl + (size_t)(m0 + r) * DMODEL + kk + c);
        }
        // W tile [32 k][128 n]: 512 uint4 per plane, 128 thr -> 4 each
#pragma unroll
        for (int i = 0; i < 4; i++) {
            int e = t + i * 128;
            int r = e >> 4, c = (e & 15) * 8;
            cp16(&Wh2[s * WSTG + r * P1W + c], Wh + (size_t)(kk + r) * DMODEL + n0 + c);
            cp16(&Wl2[s * WSTG + r * P1W + c], Wl + (size_t)(kk + r) * DMODEL + n0 + c);
        }
        CP_COMMIT;
    };

    issue_stage(0, 0);
    const int NIT = DMODEL / 32;  // 24
    for (int it = 0; it < NIT; it++) {
        if (it + 1 < NIT) {
            issue_stage((it + 1) & 1, (it + 1) * 32);
            CP_WAIT1;
        } else {
            CP_WAIT0;
        }
        __syncthreads();

        const __nv_bfloat16* xh = Xh + (it & 1) * XSTG;
        const __nv_bfloat16* xl = Xl + (it & 1) * XSTG;
        const __nv_bfloat16* wh2 = Wh2 + (it & 1) * WSTG;
        const __nv_bfloat16* wl2 = Wl2 + (it & 1) * WSTG;
#pragma unroll
        for (int ks = 0; ks < 2; ks++) {
            const int acol = ks * 16 + (lane >> 4) * 8;
            uint32_t a[4][4], bh[8][2], bl[8][2];
            ldA<P1X, 4>(xh, arow, acol, a);
            ldBT<P1W, 4>(wh2, ks * 16, wn, lane, bh);
            mma_tiles<4, 8>(acc, a, bh);
            ldBT<P1W, 4>(wl2, ks * 16, wn, lane, bl);
            mma_tiles<4, 8>(acc, a, bl);
            ldA<P1X, 4>(xl, arow, acol, a);
            mma_tiles<4, 8>(acc, a, bh);
        }
        __syncthreads();
    }

    const int g = lane >> 2, tig = lane & 3;
#pragma unroll
    for (int mt = 0; mt < 4; mt++) {
        int row = m0 + wm + mt * 16 + g;
#pragma unroll
        for (int nt = 0; nt < 8; nt++) {
            int col = n0 + wn + nt * 8 + 2 * tig;
            __nv_bfloat16 h0, l0, h1, l1;
            split2(acc[mt][nt][0] * scale, h0, l0);
            split2(acc[mt][nt][1] * scale, h1, l1);
            *(__nv_bfloat162*)(Ch + (size_t)row * DMODEL + col) = __halves2bfloat162(h0, h1);
            *(__nv_bfloat162*)(Cl + (size_t)row * DMODEL + col) = __halves2bfloat162(l0, l1);
            split2(acc[mt][nt][2] * scale, h0, l0);
            split2(acc[mt][nt][3] * scale, h1, l1);
            *(__nv_bfloat162*)(Ch + (size_t)(row + 8) * DMODEL + col) = __halves2bfloat162(h0, h1);
            *(__nv_bfloat162*)(Cl + (size_t)(row + 8) * DMODEL + col) = __halves2bfloat162(l0, l1);
        }
    }
}

// ============================================================
// Kernel 2: scores for ONE batch. 128x128 tile, K=64 resident.
// 256 thr, 8 warps of 64x32. B-hi kept live.
// ============================================================
#define P2 72

__global__ __launch_bounds__(256) void scores_kernel(int b) {
    extern __shared__ __align__(16) __nv_bfloat16 sm2[];
    __nv_bfloat16* Qh = sm2;
    __nv_bfloat16* Ql = Qh + 128 * P2;
    __nv_bfloat16* Kh2 = Ql + 128 * P2;
    __nv_bfloat16* Kl2 = Kh2 + 128 * P2;

    const int h = blockIdx.z;
    const int i0 = blockIdx.y * 128;
    const int j0 = blockIdx.x * 128;

    const int t = threadIdx.x, lane = t & 31, w = t >> 5;
    const int wm = (w & 1) * 64, wn = (w >> 1) * 32;

    const __nv_bfloat16* qhb = g_qh + (size_t)b * SEQ * DMODEL + h * DHEAD;
    const __nv_bfloat16* qlb = g_ql + (size_t)b * SEQ * DMODEL + h * DHEAD;
    const __nv_bfloat16* khb = g_kh + (size_t)b * SEQ * DMODEL + h * DHEAD;
    const __nv_bfloat16* klb = g_kl + (size_t)b * SEQ * DMODEL + h * DHEAD;

#pragma unroll
    for (int e = t; e < 1024; e += 256) {
        int r = e >> 3, c = (e & 7) * 8;
        *(uint4*)&Qh[r * P2 + c] = *(const uint4*)(qhb + (size_t)(i0 + r) * DMODEL + c);
        *(uint4*)&Ql[r * P2 + c] = *(const uint4*)(qlb + (size_t)(i0 + r) * DMODEL + c);
        *(uint4*)&Kh2[r * P2 + c] = *(const uint4*)(khb + (size_t)(j0 + r) * DMODEL + c);
        *(uint4*)&Kl2[r * P2 + c] = *(const uint4*)(klb + (size_t)(j0 + r) * DMODEL + c);
    }
    __syncthreads();

    float acc[4][4][4] = {};
    const int arow = wm + (lane & 15);
    const int bro = wn + (lane & 7) + (lane >> 4) * 8;

#pragma unroll
    for (int ks = 0; ks < 4; ks++) {
        const int acol = ks * 16 + (lane >> 4) * 8;
        const int bcol = ks * 16 + ((lane >> 3) & 1) * 8;
        uint32_t a[4][4], bh[4][2], bl[4][2];
        ldA<P2, 4>(Qh, arow, acol, a);
        ldB<P2, 2>(Kh2, bro, bcol, bh);
        mma_tiles<4, 4>(acc, a, bh);
        ldB<P2, 2>(Kl2, bro, bcol, bl);
        mma_tiles<4, 4>(acc, a, bl);
        ldA<P2, 4>(Ql, arow, acol, a);
        mma_tiles<4, 4>(acc, a, bh);
    }

    float* Sb = g_attn + (size_t)(b * NHEAD + h) * SEQ * SEQ;
    const int g = lane >> 2, tig = lane & 3;
#pragma unroll
    for (int mt = 0; mt < 4; mt++) {
        int row = i0 + wm + mt * 16 + g;
#pragma unroll
        for (int nt = 0; nt < 4; nt++) {
            int col = j0 + wn + nt * 8 + 2 * tig;
            *(float2*)(Sb + (size_t)row * SEQ + col) =
                make_float2(acc[mt][nt][0], acc[mt][nt][1]);
            *(float2*)(Sb + (size_t)(row + 8) * SEQ + col) =
                make_float2(acc[mt][nt][2], acc[mt][nt][3]);
        }
    }
}

// ============================================================
// Kernel 3: softmax (FFMA exp, no max pass) + theta mix + LN.
// 256 thr, each owns 4 consecutive k. float4 I/O.
// ============================================================
#define NW3 8

template <int V>
__device__ __forceinline__ void blockReduceSumV(float v[V], float* red, float* red2) {
    const int lane = threadIdx.x & 31, w = threadIdx.x >> 5;
#pragma unroll
    for (int h = 0; h < V; h++)
#pragma unroll
        for (int o = 16; o; o >>= 1)
            v[h] += __shfl_xor_sync(0xffffffffu, v[h], o);
    if (lane == 0) {
#pragma unroll
        for (int h = 0; h < V; h++) red[h * NW3 + w] = v[h];
    }
    __syncthreads();
    if (w < V / 4) {
        int val = 4 * w + (lane >> 3);
        float s = red[val * NW3 + (lane & 7)];
#pragma unroll
        for (int o = 4; o; o >>= 1) s += __shfl_xor_sync(0xffffffffu, s, o);
        if ((lane & 7) == 0) red2[val] = s;
    }
    __syncthreads();
#pragma unroll
    for (int h = 0; h < V; h++) v[h] = red2[h];
    __syncthreads();
}

__global__ __launch_bounds__(256) void softmax_theta_ln_kernel(
    int b, const float* __restrict__ theta,
    const float* __restrict__ lnS, const float* __restrict__ lnB) {
    __shared__ float th[144];
    __shared__ float red[24 * NW3];
    __shared__ float red2[24];

    const int qi = blockIdx.x;
    const int t = threadIdx.x;  // owns k = 4t .. 4t+3

    if (t < 144) th[t] = theta[t];

    float4 r[NHEAD];
#pragma unroll
    for (int h = 0; h < NHEAD; h++) {
        const float* src = g_attn + ((size_t)(b * NHEAD + h) * SEQ + qi) * SEQ;
        r[h] = *(const float4*)(src + 4 * t);
    }
    float4 s4 = *(const float4*)(lnS + 4 * t);
    float4 b4 = *(const float4*)(lnB + 4 * t);
    __syncthreads();

    float sum[NHEAD];
#pragma unroll
    for (int h = 0; h < NHEAD; h++) {
        r[h].x = fast_exp(r[h].x);
        r[h].y = fast_exp(r[h].y);
        r[h].z = fast_exp(r[h].z);
        r[h].w = fast_exp(r[h].w);
        sum[h] = (r[h].x + r[h].y) + (r[h].z + r[h].w);
    }
    blockReduceSumV<12>(sum, red, red2);
#pragma unroll
    for (int h = 0; h < NHEAD; h++) {
        float inv = 1.0f / sum[h];
        r[h].x *= inv;
        r[h].y *= inv;
        r[h].z *= inv;
        r[h].w *= inv;
    }

    float4 a[NHEAD];
#pragma unroll
    for (int i = 0; i < NHEAD; i++) {
        float ax = 0.f, ay = 0.f, az = 0.f, aw = 0.f;
#pragma unroll
        for (int h = 0; h < NHEAD; h++) {
            float wv = th[h * NHEAD + i];
            ax += wv * r[h].x;
            ay += wv * r[h].y;
            az += wv * r[h].z;
            aw += wv * r[h].w;
        }
        a[i] = make_float4(ax, ay, az, aw);
    }

    float st[24];
#pragma unroll
    for (int i = 0; i < NHEAD; i++) {
        st[i] = (a[i].x + a[i].y) + (a[i].z + a[i].w);
        st[12 + i] = (a[i].x * a[i].x + a[i].y * a[i].y) +
                     (a[i].z * a[i].z + a[i].w * a[i].w);
    }
    blockReduceSumV<24>(st, red, red2);

#pragma unroll
    for (int i = 0; i < NHEAD; i++) {
        float mean = st[i] * (1.0f / SEQ);
        float var = st[12 + i] * (1.0f / SEQ) - mean * mean;
        float rstd = rsqrtf(var + 1e-6f);
        size_t off = ((size_t)(b * NHEAD + i) * SEQ + qi) * SEQ + 4 * t;
        float4 o;
        o.x = (a[i].x - mean) * rstd * s4.x + b4.x;
        o.y = (a[i].y - mean) * rstd * s4.y + b4.y;
        o.z = (a[i].z - mean) * rstd * s4.z + b4.z;
        o.w = (a[i].w - mean) * rstd * s4.w + b4.w;
        split_store4(o, g_ah + off, g_al + off);
    }
}

// ============================================================
// Kernel 4: out (ALL batches). 128(k) x 64(d), q-chunk 32,
// 128 thr, 4 warps of 64(k)x32(d). cp.async double-buffered.
// ============================================================
#define PA 136
#define PV 72
#define ASTG (32 * PA)  // 4352 el
#define VSTG (32 * PV)  // 2304 el
#define OUT_SMEM ((2 * 2 * ASTG + 2 * 2 * VSTG) * 2)  // bytes

__global__ __launch_bounds__(128) void out_gemm_kernel(float* __restrict__ out) {
    extern __shared__ __align__(16) char dynsm4[];
    __nv_bfloat16* Ahs = (__nv_bfloat16*)dynsm4;  // [2][ASTG]
    __nv_bfloat16* Als = Ahs + 2 * ASTG;
    __nv_bfloat16* Vhs = Als + 2 * ASTG;          // [2][VSTG]
    __nv_bfloat16* Vls = Vhs + 2 * VSTG;

    const int bh = blockIdx.y;
    const int b = bh / NHEAD, h = bh % NHEAD;
    const int k0b = blockIdx.x * 128;

    const int t = threadIdx.x, lane = t & 31, w = t >> 5;
    const int wm = (w & 1) * 64;   // k-dim
    const int wn = (w >> 1) * 32;  // d-dim

    const __nv_bfloat16* ahb = g_ah + (size_t)(b * NHEAD + h) * SEQ * SEQ;
    const __nv_bfloat16* alb = g_al + (size_t)(b * NHEAD + h) * SEQ * SEQ;
    const __nv_bfloat16* vhb = g_vh + (size_t)b * SEQ * DMODEL + h * DHEAD;
    const __nv_bfloat16* vlb = g_vl + (size_t)b * SEQ * DMODEL + h * DHEAD;

    float acc[4][4][4] = {};

    auto issue_stage = [&](int s, int q0) {
#pragma unroll
        for (int i = 0; i < 4; i++) {
            int idx = t + i * 128;
            int r = idx >> 4, c = (idx & 15) * 8;
            cp16(&Ahs[s * ASTG + r * PA + c], ahb + (size_t)(q0 + r) * SEQ + k0b + c);
            cp16(&Als[s * ASTG + r * PA + c], alb + (size_t)(q0 + r) * SEQ + k0b + c);
        }
#pragma unroll
        for (int i = 0; i < 2; i++) {
            int idx = t + i * 128;
            int r = idx >> 3, c = (idx & 7) * 8;
            cp16(&Vhs[s * VSTG + r * PV + c], vhb + (size_t)(q0 + r) * DMODEL + c);
            cp16(&Vls[s * VSTG + r * PV + c], vlb + (size_t)(q0 + r) * DMODEL + c);
        }
        CP_COMMIT;
    };

    issue_stage(0, 0);
    const int NIT = SEQ / 32;  // 32
    for (int it = 0; it < NIT; it++) {
        if (it + 1 < NIT) {
            issue_stage((it + 1) & 1, (it + 1) * 32);
            CP_WAIT1;
        } else {
            CP_WAIT0;
        }
        __syncthreads();

        const __nv_bfloat16* ah = Ahs + (it & 1) * ASTG;
        const __nv_bfloat16* al = Als + (it & 1) * ASTG;
        const __nv_bfloat16* vh = Vhs + (it & 1) * VSTG;
        const __nv_bfloat16* vl = Vls + (it & 1) * VSTG;
#pragma unroll
        for (int ks = 0; ks < 2; ks++) {
            const int qc = ks * 16;
            uint32_t a[4][4], bh2[4][2], bl2[4][2];
            ldAT<PA, 4>(ah, qc, wm, lane, a);
            ldBT<PV, 2>(vh, qc, wn, lane, bh2);
            mma_tiles<4, 4>(acc, a, bh2);
            ldBT<PV, 2>(vl, qc, wn, lane, bl2);
            mma_tiles<4, 4>(acc, a, bl2);
            ldAT<PA, 4>(al, qc, wm, lane, a);
            mma_tiles<4, 4>(acc, a, bh2);
        }
        __syncthreads();
    }

    const int g = lane >> 2, tig = lane & 3;
#pragma unroll
    for (int mt = 0; mt < 4; mt++) {
        int row = k0b + wm + mt * 16 + g;
#pragma unroll
        for (int nt = 0; nt < 4; nt++) {
            int col = h * DHEAD + wn + nt * 8 + 2 * tig;
            *(float2*)(out + (size_t)(b * SEQ + row) * DMODEL + col) =
                make_float2(acc[mt][nt][0], acc[mt][nt][1]);
            *(float2*)(out + (size_t)(b * SEQ + row + 8) * DMODEL + col) =
                make_float2(acc[mt][nt][2], acc[mt][nt][3]);
        }
    }
}

// ============================================================
extern "C" void kernel_launch(void* const* d_in, const int* in_sizes, int n_in,
                              void* d_out, int out_size) {
    const float* x     = (const float*)d_in[0];
    const float* Wq    = (const float*)d_in[1];
    const float* Wk    = (const float*)d_in[2];
    const float* Wv    = (const float*)d_in[3];
    const float* theta = (const float*)d_in[4];
    const float* lnS   = (const float*)d_in[5];
    const float* lnB   = (const float*)d_in[6];
    float* out = (float*)d_out;

    // 0. convert inputs to bf16 hi/lo planes.
    const int X4 = BN * DMODEL / 4;
    convert_x_kernel<<<X4 / 2 / 256, 256>>>(x, 0);
    convert_x_kernel<<<X4 / 2 / 256, 256>>>(x, X4 / 2);
    {
        dim3 grid(DMODEL * DMODEL / 4 / 256, 1, 3);
        convert_w_kernel<<<grid, 256>>>(Wq, Wk, Wv);
    }
    // 1. QKV projections (128x128 CTA, 4 warps of 64x64, 2 CTA/SM)
    {
        cudaFuncSetAttribute(qkv_gemm_kernel,
                             cudaFuncAttributeMaxDynamicSharedMemorySize, QKV_SMEM);
        dim3 grid(DMODEL / 128, BN / 128, 3);
        qkv_gemm_kernel<<<grid, 128, QKV_SMEM>>>();
    }
    // 2-3. per-batch scores -> softmax pairs: S (48 MB/batch) stays in L2
    int smem = 4 * 128 * P2 * sizeof(__nv_bfloat16);  // 73728 B
    cudaFuncSetAttribute(scores_kernel,
                         cudaFuncAttributeMaxDynamicSharedMemorySize, smem);
    for (int b = 0; b < BATCH; b++) {
        dim3 grid2(SEQ / 128, SEQ / 128, NHEAD);
        scores_kernel<<<grid2, 256, smem>>>(b);
        softmax_theta_ln_kernel<<<SEQ, 256>>>(b, theta, lnS, lnB);
    }
    // 4. output GEMM, full batch (384 CTAs), cp.async pipelined
    {
        cudaFuncSetAttribute(out_gemm_kernel,
                             cudaFuncAttributeMaxDynamicSharedMemorySize, OUT_SMEM);
        dim3 grid4(SEQ / 128, BATCH * NHEAD);
        out_gemm_kernel<<<grid4, 128, OUT_SMEM>>>(out);
    }
}

// round 15
// speedup vs baseline: 1.2539x; 1.1194x over previous
#include <cuda_runtime.h>
#include <cuda_bf16.h>
#include <math.h>
#include <stdint.h>

#define BATCH 4
#define SEQ 1024
#define DMODEL 768
#define NHEAD 12
#define DHEAD 64
#define BN (BATCH*SEQ)

// ---- scratch (static device globals; no allocation) ----
__device__ float g_attn[(size_t)BATCH * NHEAD * SEQ * SEQ];        // fp32 S
__device__ __nv_bfloat16 g_ah[(size_t)BATCH * NHEAD * SEQ * SEQ];  // A hi
__device__ __nv_bfloat16 g_al[(size_t)BATCH * NHEAD * SEQ * SEQ];  // A lo
__device__ __nv_bfloat16 g_qh[BN * DMODEL], g_ql[BN * DMODEL];
__device__ __nv_bfloat16 g_kh[BN * DMODEL], g_kl[BN * DMODEL];
__device__ __nv_bfloat16 g_vh[BN * DMODEL], g_vl[BN * DMODEL];
__device__ __nv_bfloat16 g_xh[BN * DMODEL], g_xl[BN * DMODEL];
__device__ __nv_bfloat16 g_wh[3 * DMODEL * DMODEL], g_wl[3 * DMODEL * DMODEL];

// ============================================================
// helpers
// ============================================================
__device__ __forceinline__ uint32_t smem_u32(const void* p) {
    return (uint32_t)__cvta_generic_to_shared(p);
}

__device__ __forceinline__ void cp16(void* smem, const void* gmem) {
    asm volatile("cp.async.cg.shared.global [%0], [%1], 16;\n" ::"r"(smem_u32(smem)),
                 "l"(gmem));
}
#define CP_COMMIT asm volatile("cp.async.commit_group;\n" ::)
#define CP_WAIT0 asm volatile("cp.async.wait_group 0;\n" ::)
#define CP_WAIT1 asm volatile("cp.async.wait_group 1;\n" ::)

__device__ __forceinline__ void ldsm4(uint32_t addr, uint32_t* r) {
    asm volatile("ldmatrix.sync.aligned.m8n8.x4.shared.b16 {%0,%1,%2,%3}, [%4];\n"
                 : "=r"(r[0]), "=r"(r[1]), "=r"(r[2]), "=r"(r[3])
                 : "r"(addr));
}

__device__ __forceinline__ void ldsm4t(uint32_t addr, uint32_t* r) {
    asm volatile("ldmatrix.sync.aligned.m8n8.x4.trans.shared.b16 {%0,%1,%2,%3}, [%4];\n"
                 : "=r"(r[0]), "=r"(r[1]), "=r"(r[2]), "=r"(r[3])
                 : "r"(addr));
}

__device__ __forceinline__ void mma_bf16(float* c, const uint32_t* a, const uint32_t* b) {
    asm volatile(
        "mma.sync.aligned.m16n8k16.row.col.f32.bf16.bf16.f32 "
        "{%0,%1,%2,%3}, {%4,%5,%6,%7}, {%8,%9}, {%0,%1,%2,%3};\n"
        : "+f"(c[0]), "+f"(c[1]), "+f"(c[2]), "+f"(c[3])
        : "r"(a[0]), "r"(a[1]), "r"(a[2]), "r"(a[3]), "r"(b[0]), "r"(b[1]));
}

__device__ __forceinline__ void split2(float v, __nv_bfloat16& h, __nv_bfloat16& l) {
    h = __float2bfloat16(v);
    l = __float2bfloat16(v - __bfloat162float(h));
}

__device__ __forceinline__ uint32_t bpack(__nv_bfloat16 a, __nv_bfloat16 b) {
    __nv_bfloat162 p = __halves2bfloat162(a, b);
    return *reinterpret_cast<uint32_t*>(&p);
}

__device__ __forceinline__ void split_store4(float4 v, __nv_bfloat16* H,
                                             __nv_bfloat16* L) {
    __nv_bfloat16 h0, h1, h2, h3, l0, l1, l2, l3;
    split2(v.x, h0, l0);
    split2(v.y, h1, l1);
    split2(v.z, h2, l2);
    split2(v.w, h3, l3);
    *reinterpret_cast<uint2*>(H) = make_uint2(bpack(h0, h1), bpack(h2, h3));
    *reinterpret_cast<uint2*>(L) = make_uint2(bpack(l0, l1), bpack(l2, l3));
}

// ---- packed f32x2 ops (Blackwell FFMA2 path) ----
__device__ __forceinline__ uint64_t pk2(float lo, float hi) {
    uint64_t d;
    asm("mov.b64 %0, {%1, %2};" : "=l"(d) : "f"(lo), "f"(hi));
    return d;
}
__device__ __forceinline__ void upk2(uint64_t v, float& lo, float& hi) {
    asm("mov.b64 {%0, %1}, %2;" : "=f"(lo), "=f"(hi) : "l"(v));
}
__device__ __forceinline__ uint64_t ffma2(uint64_t a, uint64_t b, uint64_t c) {
    uint64_t d;
    asm("fma.rn.f32x2 %0, %1, %2, %3;" : "=l"(d) : "l"(a), "l"(b), "l"(c));
    return d;
}
__device__ __forceinline__ uint64_t fmul2(uint64_t a, uint64_t b) {
    uint64_t d;
    asm("mul.rn.f32x2 %0, %1, %2;" : "=l"(d) : "l"(a), "l"(b));
    return d;
}

template <int PITCH, int MT>
__device__ __forceinline__ void ldA(const __nv_bfloat16* P, int arow, int acol,
                                    uint32_t a[][4]) {
#pragma unroll
    for (int mt = 0; mt < MT; mt++)
        ldsm4(smem_u32(P + (arow + mt * 16) * PITCH + acol), a[mt]);
}

template <int PITCH, int NP>
__device__ __forceinline__ void ldB(const __nv_bfloat16* P, int brow, int bcol,
                                    uint32_t b[][2]) {
#pragma unroll
    for (int p = 0; p < NP; p++) {
        uint32_t r[4];
        ldsm4(smem_u32(P + (brow + p * 16) * PITCH + bcol), r);
        b[2 * p][0] = r[0];
        b[2 * p][1] = r[1];
        b[2 * p + 1][0] = r[2];
        b[2 * p + 1][1] = r[3];
    }
}

// A fragments via trans: smem holds A^T as [K][m]
template <int PITCH, int MT>
__device__ __forceinline__ void ldAT(const __nv_bfloat16* P, int kc, int m0,
                                     int lane, uint32_t a[][4]) {
    const int row = kc + (lane & 7) + ((lane >> 4) & 1) * 8;
    const int cb = ((lane >> 3) & 1) * 8;
#pragma unroll
    for (int mt = 0; mt < MT; mt++)
        ldsm4t(smem_u32(P + row * PITCH + m0 + mt * 16 + cb), a[mt]);
}

// B fragments via trans: smem holds B as [K][n]
template <int PITCH, int NP>
__device__ __forceinline__ void ldBT(const __nv_bfloat16* P, int kc, int n0,
                                     int lane, uint32_t b[][2]) {
    const int row = kc + (lane & 7) + ((lane >> 3) & 1) * 8;
    const int cb = ((lane >> 4) & 1) * 8;
#pragma unroll
    for (int p = 0; p < NP; p++) {
        uint32_t r[4];
        ldsm4t(smem_u32(P + row * PITCH + n0 + p * 16 + cb), r);
        b[2 * p][0] = r[0];
        b[2 * p][1] = r[1];
        b[2 * p + 1][0] = r[2];
        b[2 * p + 1][1] = r[3];
    }
}

template <int MT, int NT>
__device__ __forceinline__ void mma_tiles(float (*acc)[NT][4], uint32_t a[][4],
                                          uint32_t b[][2]) {
#pragma unroll
    for (int mt = 0; mt < MT; mt++)
#pragma unroll
        for (int nt = 0; nt < NT; nt++) mma_bf16(acc[mt][nt], a[mt], b[nt]);
}

// ============================================================
// Kernel 0a/0b: one-pass fp32 -> bf16 hi/lo plane converters
// ============================================================
__global__ __launch_bounds__(256) void convert_x_kernel(const float* __restrict__ x,
                                                        int base4) {
    int idx = base4 + blockIdx.x * 256 + threadIdx.x;
    float4 v = *(const float4*)(x + (size_t)idx * 4);
    split_store4(v, g_xh + (size_t)idx * 4, g_xl + (size_t)idx * 4);
}

__global__ __launch_bounds__(256) void convert_w_kernel(
    const float* __restrict__ Wq, const float* __restrict__ Wk,
    const float* __restrict__ Wv) {
    const int z = blockIdx.z;
    const float* __restrict__ W = (z == 0) ? Wq : (z == 1) ? Wk : Wv;
    size_t base = (size_t)z * DMODEL * DMODEL;
    int idx = blockIdx.x * 256 + threadIdx.x;
    float4 v = *(const float4*)(W + (size_t)idx * 4);
    split_store4(v, g_wh + base + (size_t)idx * 4, g_wl + base + (size_t)idx * 4);
}

// ============================================================
// Kernel 1: QKV projections. CTA 128(m) x 128(n), BK=32,
// 4 warps of 64x64, 128 thr, cp.async double-buffered,
// 2 CTAs/SM for barrier overlap.
// ============================================================
#define P1X 40
#define P1W 136
#define XSTG (128 * P1X)  // 5120 el
#define WSTG (32 * P1W)   // 4352 el
#define QKV_SMEM ((2 * 2 * XSTG + 2 * 2 * WSTG) * 2)  // 75776 B

__global__ __launch_bounds__(128, 2) void qkv_gemm_kernel() {
    extern __shared__ __align__(16) char dynsm[];
    __nv_bfloat16* Xh = (__nv_bfloat16*)dynsm;   // [2][XSTG]
    __nv_bfloat16* Xl = Xh + 2 * XSTG;
    __nv_bfloat16* Wh2 = Xl + 2 * XSTG;          // [2][WSTG]
    __nv_bfloat16* Wl2 = Wh2 + 2 * WSTG;

    const int z = blockIdx.z;
    const __nv_bfloat16* __restrict__ Wh = g_wh + (size_t)z * DMODEL * DMODEL;
    const __nv_bfloat16* __restrict__ Wl = g_wl + (size_t)z * DMODEL * DMODEL;
    __nv_bfloat16* Ch = (z == 0) ? g_qh : (z == 1) ? g_kh : g_vh;
    __nv_bfloat16* Cl = (z == 0) ? g_ql : (z == 1) ? g_kl : g_vl;
    const float scale = (z == 0) ? 0.125f : 1.0f;

    const int m0 = blockIdx.y * 128;
    const int n0 = blockIdx.x * 128;

    const int t = threadIdx.x, lane = t & 31, w = t >> 5;
    const int wm = (w & 1) * 64;   // m: 2 x 64
    const int wn = (w >> 1) * 64;  // n: 2 x 64

    float acc[4][8][4] = {};
    const int arow = wm + (lane & 15);

    auto issue_stage = [&](int s, int kk) {
        // X tile [128 m][32 k]: 512 uint4 per plane, 128 thr -> 4 each
#pragma unroll
        for (int i = 0; i < 4; i++) {
            int e = t + i * 128;
            int r = e >> 2, c = (e & 3) * 8;
            cp16(&Xh[s * XSTG + r * P1X + c], g_xh + (size_t)(m0 + r) * DMODEL + kk + c);
            cp16(&Xl[s * XSTG + r * P1X + c], g_xl + (size_t)(m0 + r) * DMODEL + kk + c);
        }
        // W tile [32 k][128 n]: 512 uint4 per plane, 128 thr -> 4 each
#pragma unroll
        for (int i = 0; i < 4; i++) {
            int e = t + i * 128;
            int r = e >> 4, c = (e & 15) * 8;
            cp16(&Wh2[s * WSTG + r * P1W + c], Wh + (size_t)(kk + r) * DMODEL + n0 + c);
            cp16(&Wl2[s * WSTG + r * P1W + c], Wl + (size_t)(kk + r) * DMODEL + n0 + c);
        }
        CP_COMMIT;
    };

    issue_stage(0, 0);
    const int NIT = DMODEL / 32;  // 24
    for (int it = 0; it < NIT; it++) {
        if (it + 1 < NIT) {
            issue_stage((it + 1) & 1, (it + 1) * 32);
            CP_WAIT1;
        } else {
            CP_WAIT0;
        }
        __syncthreads();

        const __nv_bfloat16* xh = Xh + (it & 1) * XSTG;
        const __nv_bfloat16* xl = Xl + (it & 1) * XSTG;
        const __nv_bfloat16* wh2 = Wh2 + (it & 1) * WSTG;
        const __nv_bfloat16* wl2 = Wl2 + (it & 1) * WSTG;
#pragma unroll
        for (int ks = 0; ks < 2; ks++) {
            const int acol = ks * 16 + (lane >> 4) * 8;
            uint32_t a[4][4], bh[8][2], bl[8][2];
            ldA<P1X, 4>(xh, arow, acol, a);
            ldBT<P1W, 4>(wh2, ks * 16, wn, lane, bh);
            mma_tiles<4, 8>(acc, a, bh);
            ldBT<P1W, 4>(wl2, ks * 16, wn, lane, bl);
            mma_tiles<4, 8>(acc, a, bl);
            ldA<P1X, 4>(xl, arow, acol, a);
            mma_tiles<4, 8>(acc, a, bh);
        }
        __syncthreads();
    }

    const int g = lane >> 2, tig = lane & 3;
#pragma unroll
    for (int mt = 0; mt < 4; mt++) {
        int row = m0 + wm + mt * 16 + g;
#pragma unroll
        for (int nt = 0; nt < 8; nt++) {
            int col = n0 + wn + nt * 8 + 2 * tig;
            __nv_bfloat16 h0, l0, h1, l1;
            split2(acc[mt][nt][0] * scale, h0, l0);
            split2(acc[mt][nt][1] * scale, h1, l1);
            *(__nv_bfloat162*)(Ch + (size_t)row * DMODEL + col) = __halves2bfloat162(h0, h1);
            *(__nv_bfloat162*)(Cl + (size_t)row * DMODEL + col) = __halves2bfloat162(l0, l1);
            split2(acc[mt][nt][2] * scale, h0, l0);
            split2(acc[mt][nt][3] * scale, h1, l1);
            *(__nv_bfloat162*)(Ch + (size_t)(row + 8) * DMODEL + col) = __halves2bfloat162(h0, h1);
            *(__nv_bfloat162*)(Cl + (size_t)(row + 8) * DMODEL + col) = __halves2bfloat162(l0, l1);
        }
    }
}

// ============================================================
// Kernel 2: scores for ONE batch. 128x128 tile, K=64 resident.
// 256 thr, 8 warps of 64x32. B-hi kept live.
// ============================================================
#define P2 72

__global__ __launch_bounds__(256) void scores_kernel(int b) {
    extern __shared__ __align__(16) __nv_bfloat16 sm2[];
    __nv_bfloat16* Qh = sm2;
    __nv_bfloat16* Ql = Qh + 128 * P2;
    __nv_bfloat16* Kh2 = Ql + 128 * P2;
    __nv_bfloat16* Kl2 = Kh2 + 128 * P2;

    const int h = blockIdx.z;
    const int i0 = blockIdx.y * 128;
    const int j0 = blockIdx.x * 128;

    const int t = threadIdx.x, lane = t & 31, w = t >> 5;
    const int wm = (w & 1) * 64, wn = (w >> 1) * 32;

    const __nv_bfloat16* qhb = g_qh + (size_t)b * SEQ * DMODEL + h * DHEAD;
    const __nv_bfloat16* qlb = g_ql + (size_t)b * SEQ * DMODEL + h * DHEAD;
    const __nv_bfloat16* khb = g_kh + (size_t)b * SEQ * DMODEL + h * DHEAD;
    const __nv_bfloat16* klb = g_kl + (size_t)b * SEQ * DMODEL + h * DHEAD;

#pragma unroll
    for (int e = t; e < 1024; e += 256) {
        int r = e >> 3, c = (e & 7) * 8;
        *(uint4*)&Qh[r * P2 + c] = *(const uint4*)(qhb + (size_t)(i0 + r) * DMODEL + c);
        *(uint4*)&Ql[r * P2 + c] = *(const uint4*)(qlb + (size_t)(i0 + r) * DMODEL + c);
        *(uint4*)&Kh2[r * P2 + c] = *(const uint4*)(khb + (size_t)(j0 + r) * DMODEL + c);
        *(uint4*)&Kl2[r * P2 + c] = *(const uint4*)(klb + (size_t)(j0 + r) * DMODEL + c);
    }
    __syncthreads();

    float acc[4][4][4] = {};
    const int arow = wm + (lane & 15);
    const int bro = wn + (lane & 7) + (lane >> 4) * 8;

#pragma unroll
    for (int ks = 0; ks < 4; ks++) {
        const int acol = ks * 16 + (lane >> 4) * 8;
        const int bcol = ks * 16 + ((lane >> 3) & 1) * 8;
        uint32_t a[4][4], bh[4][2], bl[4][2];
        ldA<P2, 4>(Qh, arow, acol, a);
        ldB<P2, 2>(Kh2, bro, bcol, bh);
        mma_tiles<4, 4>(acc, a, bh);
        ldB<P2, 2>(Kl2, bro, bcol, bl);
        mma_tiles<4, 4>(acc, a, bl);
        ldA<P2, 4>(Ql, arow, acol, a);
        mma_tiles<4, 4>(acc, a, bh);
    }

    float* Sb = g_attn + (size_t)(b * NHEAD + h) * SEQ * SEQ;
    const int g = lane >> 2, tig = lane & 3;
#pragma unroll
    for (int mt = 0; mt < 4; mt++) {
        int row = i0 + wm + mt * 16 + g;
#pragma unroll
        for (int nt = 0; nt < 4; nt++) {
            int col = j0 + wn + nt * 8 + 2 * tig;
            *(float2*)(Sb + (size_t)row * SEQ + col) =
                make_float2(acc[mt][nt][0], acc[mt][nt][1]);
            *(float2*)(Sb + (size_t)(row + 8) * SEQ + col) =
                make_float2(acc[mt][nt][2], acc[mt][nt][3]);
        }
    }
}

// ============================================================
// Kernel 3: softmax (MUFU exp, no max pass) + packed-f32x2 theta
// mix + LN. 256 thr, each owns 4 consecutive k.
// ============================================================
#define NW3 8

template <int V>
__device__ __forceinline__ void blockReduceSumV(float v[V], float* red, float* red2) {
    const int lane = threadIdx.x & 31, w = threadIdx.x >> 5;
#pragma unroll
    for (int h = 0; h < V; h++)
#pragma unroll
        for (int o = 16; o; o >>= 1)
            v[h] += __shfl_xor_sync(0xffffffffu, v[h], o);
    if (lane == 0) {
#pragma unroll
        for (int h = 0; h < V; h++) red[h * NW3 + w] = v[h];
    }
    __syncthreads();
    if (w < V / 4) {
        int val = 4 * w + (lane >> 3);
        float s = red[val * NW3 + (lane & 7)];
#pragma unroll
        for (int o = 4; o; o >>= 1) s += __shfl_xor_sync(0xffffffffu, s, o);
        if ((lane & 7) == 0) red2[val] = s;
    }
    __syncthreads();
#pragma unroll
    for (int h = 0; h < V; h++) v[h] = red2[h];
    __syncthreads();
}

__global__ __launch_bounds__(256) void softmax_theta_ln_kernel(
    int b, const float* __restrict__ theta,
    const float* __restrict__ lnS, const float* __restrict__ lnB) {
    __shared__ uint64_t th2[144];  // theta broadcast-packed (w,w)
    __shared__ float red[24 * NW3];
    __shared__ float red2[24];

    const int qi = blockIdx.x;
    const int t = threadIdx.x;  // owns k = 4t .. 4t+3

    if (t < 144) {
        float wv = theta[t];
        th2[t] = pk2(wv, wv);
    }

    float4 r[NHEAD];
#pragma unroll
    for (int h = 0; h < NHEAD; h++) {
        const float* src = g_attn + ((size_t)(b * NHEAD + h) * SEQ + qi) * SEQ;
        r[h] = *(const float4*)(src + 4 * t);
    }
    float4 s4 = *(const float4*)(lnS + 4 * t);
    float4 b4 = *(const float4*)(lnB + 4 * t);
    __syncthreads();

    // softmax without max subtraction; MUFU exp (overlaps FMA pipe)
    float sum[NHEAD];
#pragma unroll
    for (int h = 0; h < NHEAD; h++) {
        r[h].x = __expf(r[h].x);
        r[h].y = __expf(r[h].y);
        r[h].z = __expf(r[h].z);
        r[h].w = __expf(r[h].w);
        sum[h] = (r[h].x + r[h].y) + (r[h].z + r[h].w);
    }
    blockReduceSumV<12>(sum, red, red2);

    // normalized probabilities, packed as f32x2 pairs
    uint64_t pxy[NHEAD], pzw[NHEAD];
#pragma unroll
    for (int h = 0; h < NHEAD; h++) {
        float inv = 1.0f / sum[h];
        uint64_t inv2 = pk2(inv, inv);
        pxy[h] = fmul2(pk2(r[h].x, r[h].y), inv2);
        pzw[h] = fmul2(pk2(r[h].z, r[h].w), inv2);
    }

    // theta head-mix with packed FFMA2: a_i = sum_h theta[h,i] * p_h
    uint64_t axy[NHEAD], azw[NHEAD];
#pragma unroll
    for (int i = 0; i < NHEAD; i++) {
        uint64_t sx = fmul2(th2[i], pxy[0]);
        uint64_t sz = fmul2(th2[i], pzw[0]);
#pragma unroll
        for (int h = 1; h < NHEAD; h++) {
            sx = ffma2(th2[h * NHEAD + i], pxy[h], sx);
            sz = ffma2(th2[h * NHEAD + i], pzw[h], sz);
        }
        axy[i] = sx;
        azw[i] = sz;
    }

    // LN stats
    float st[24];
#pragma unroll
    for (int i = 0; i < NHEAD; i++) {
        float ax, ay, az, aw;
        upk2(axy[i], ax, ay);
        upk2(azw[i], az, aw);
        st[i] = (ax + ay) + (az + aw);
        st[12 + i] = (ax * ax + ay * ay) + (az * az + aw * aw);
    }
    blockReduceSumV<24>(st, red, red2);

    const uint64_t sxy = pk2(s4.x, s4.y), szw = pk2(s4.z, s4.w);
    const uint64_t bxy = pk2(b4.x, b4.y), bzw = pk2(b4.z, b4.w);

#pragma unroll
    for (int i = 0; i < NHEAD; i++) {
        float mean = st[i] * (1.0f / SEQ);
        float var = st[12 + i] * (1.0f / SEQ) - mean * mean;
        float rstd = rsqrtf(var + 1e-6f);
        float nmr = -mean * rstd;
        uint64_t rstd2 = pk2(rstd, rstd), nmr2 = pk2(nmr, nmr);
        // o = ((a - mean)*rstd) * s + b = fma(fma(a,rstd,nmr), s, b)
        uint64_t txy = ffma2(axy[i], rstd2, nmr2);
        uint64_t tzw = ffma2(azw[i], rstd2, nmr2);
        uint64_t oxy = ffma2(txy, sxy, bxy);
        uint64_t ozw = ffma2(tzw, szw, bzw);
        float4 o;
        upk2(oxy, o.x, o.y);
        upk2(ozw, o.z, o.w);
        size_t off = ((size_t)(b * NHEAD + i) * SEQ + qi) * SEQ + 4 * t;
        split_store4(o, g_ah + off, g_al + off);
    }
}

// ============================================================
// Kernel 4: out (ALL batches). 128(k) x 64(d), q-chunk 32,
// 128 thr, 4 warps of 64(k)x32(d). cp.async double-buffered.
// ============================================================
#define PA 136
#define PV 72
#define ASTG (32 * PA)  // 4352 el
#define VSTG (32 * PV)  // 2304 el
#define OUT_SMEM ((2 * 2 * ASTG + 2 * 2 * VSTG) * 2)  // bytes

__global__ __launch_bounds__(128) void out_gemm_kernel(float* __restrict__ out) {
    extern __shared__ __align__(16) char dynsm4[];
    __nv_bfloat16* Ahs = (__nv_bfloat16*)dynsm4;  // [2][ASTG]
    __nv_bfloat16* Als = Ahs + 2 * ASTG;
    __nv_bfloat16* Vhs = Als + 2 * ASTG;          // [2][VSTG]
    __nv_bfloat16* Vls = Vhs + 2 * VSTG;

    const int bh = blockIdx.y;
    const int b = bh / NHEAD, h = bh % NHEAD;
    const int k0b = blockIdx.x * 128;

    const int t = threadIdx.x, lane = t & 31, w = t >> 5;
    const int wm = (w & 1) * 64;   // k-dim
    const int wn = (w >> 1) * 32;  // d-dim

    const __nv_bfloat16* ahb = g_ah + (size_t)(b * NHEAD + h) * SEQ * SEQ;
    const __nv_bfloat16* alb = g_al + (size_t)(b * NHEAD + h) * SEQ * SEQ;
    const __nv_bfloat16* vhb = g_vh + (size_t)b * SEQ * DMODEL + h * DHEAD;
    const __nv_bfloat16* vlb = g_vl + (size_t)b * SEQ * DMODEL + h * DHEAD;

    float acc[4][4][4] = {};

    auto issue_stage = [&](int s, int q0) {
#pragma unroll
        for (int i = 0; i < 4; i++) {
            int idx = t + i * 128;
            int r = idx >> 4, c = (idx & 15) * 8;
            cp16(&Ahs[s * ASTG + r * PA + c], ahb + (size_t)(q0 + r) * SEQ + k0b + c);
            cp16(&Als[s * ASTG + r * PA + c], alb + (size_t)(q0 + r) * SEQ + k0b + c);
        }
#pragma unroll
        for (int i = 0; i < 2; i++) {
            int idx = t + i * 128;
            int r = idx >> 3, c = (idx & 7) * 8;
            cp16(&Vhs[s * VSTG + r * PV + c], vhb + (size_t)(q0 + r) * DMODEL + c);
            cp16(&Vls[s * VSTG + r * PV + c], vlb + (size_t)(q0 + r) * DMODEL + c);
        }
        CP_COMMIT;
    };

    issue_stage(0, 0);
    const int NIT = SEQ / 32;  // 32
    for (int it = 0; it < NIT; it++) {
        if (it + 1 < NIT) {
            issue_stage((it + 1) & 1, (it + 1) * 32);
            CP_WAIT1;
        } else {
            CP_WAIT0;
        }
        __syncthreads();

        const __nv_bfloat16* ah = Ahs + (it & 1) * ASTG;
        const __nv_bfloat16* al = Als + (it & 1) * ASTG;
        const __nv_bfloat16* vh = Vhs + (it & 1) * VSTG;
        const __nv_bfloat16* vl = Vls + (it & 1) * VSTG;
#pragma unroll
        for (int ks = 0; ks < 2; ks++) {
            const int qc = ks * 16;
            uint32_t a[4][4], bh2[4][2], bl2[4][2];
            ldAT<PA, 4>(ah, qc, wm, lane, a);
            ldBT<PV, 2>(vh, qc, wn, lane, bh2);
            mma_tiles<4, 4>(acc, a, bh2);
            ldBT<PV, 2>(vl, qc, wn, lane, bl2);
            mma_tiles<4, 4>(acc, a, bl2);
            ldAT<PA, 4>(al, qc, wm, lane, a);
            mma_tiles<4, 4>(acc, a, bh2);
        }
        __syncthreads();
    }

    const int g = lane >> 2, tig = lane & 3;
#pragma unroll
    for (int mt = 0; mt < 4; mt++) {
        int row = k0b + wm + mt * 16 + g;
#pragma unroll
        for (int nt = 0; nt < 4; nt++) {
            int col = h * DHEAD + wn + nt * 8 + 2 * tig;
            *(float2*)(out + (size_t)(b * SEQ + row) * DMODEL + col) =
                make_float2(acc[mt][nt][0], acc[mt][nt][1]);
            *(float2*)(out + (size_t)(b * SEQ + row + 8) * DMODEL + col) =
                make_float2(acc[mt][nt][2], acc[mt][nt][3]);
        }
    }
}

// ============================================================
extern "C" void kernel_launch(void* const* d_in, const int* in_sizes, int n_in,
                              void* d_out, int out_size) {
    const float* x     = (const float*)d_in[0];
    const float* Wq    = (const float*)d_in[1];
    const float* Wk    = (const float*)d_in[2];
    const float* Wv    = (const float*)d_in[3];
    const float* theta = (const float*)d_in[4];
    const float* lnS   = (const float*)d_in[5];
    const float* lnB   = (const float*)d_in[6];
    float* out = (float*)d_out;

    // 0. convert inputs to bf16 hi/lo planes.
    const int X4 = BN * DMODEL / 4;
    convert_x_kernel<<<X4 / 2 / 256, 256>>>(x, 0);
    convert_x_kernel<<<X4 / 2 / 256, 256>>>(x, X4 / 2);
    {
        dim3 grid(DMODEL * DMODEL / 4 / 256, 1, 3);
        convert_w_kernel<<<grid, 256>>>(Wq, Wk, Wv);
    }
    // 1. QKV projections (128x128 CTA, 4 warps of 64x64, 2 CTA/SM)
    {
        cudaFuncSetAttribute(qkv_gemm_kernel,
                             cudaFuncAttributeMaxDynamicSharedMemorySize, QKV_SMEM);
        dim3 grid(DMODEL / 128, BN / 128, 3);
        qkv_gemm_kernel<<<grid, 128, QKV_SMEM>>>();
    }
    // 2-3. per-batch scores -> softmax pairs: S (48 MB/batch) stays in L2
    int smem = 4 * 128 * P2 * sizeof(__nv_bfloat16);  // 73728 B
    cudaFuncSetAttribute(scores_kernel,
                         cudaFuncAttributeMaxDynamicSharedMemorySize, smem);
    for (int b = 0; b < BATCH; b++) {
        dim3 grid2(SEQ / 128, SEQ / 128, NHEAD);
        scores_kernel<<<grid2, 256, smem>>>(b);
        softmax_theta_ln_kernel<<<SEQ, 256>>>(b, theta, lnS, lnB);
    }
    // 4. output GEMM, full batch (384 CTAs), cp.async pipelined
    {
        cudaFuncSetAttribute(out_gemm_kernel,
                             cudaFuncAttributeMaxDynamicSharedMemorySize, OUT_SMEM);
        dim3 grid4(SEQ / 128, BATCH * NHEAD);
        out_gemm_kernel<<<grid4, 128, OUT_SMEM>>>(out);
    }
}

// round 16
// speedup vs baseline: 1.2607x; 1.0055x over previous
#include <cuda_runtime.h>
#include <cuda_bf16.h>
#include <math.h>
#include <stdint.h>

#define BATCH 4
#define SEQ 1024
#define DMODEL 768
#define NHEAD 12
#define DHEAD 64
#define BN (BATCH*SEQ)

// ---- scratch (static device globals; no allocation) ----
__device__ float g_attn[(size_t)BATCH * NHEAD * SEQ * SEQ];        // fp32 S
__device__ __nv_bfloat16 g_ah[(size_t)BATCH * NHEAD * SEQ * SEQ];  // A hi
__device__ __nv_bfloat16 g_al[(size_t)BATCH * NHEAD * SEQ * SEQ];  // A lo
__device__ __nv_bfloat16 g_qh[BN * DMODEL], g_ql[BN * DMODEL];
__device__ __nv_bfloat16 g_kh[BN * DMODEL], g_kl[BN * DMODEL];
__device__ __nv_bfloat16 g_vh[BN * DMODEL], g_vl[BN * DMODEL];
__device__ __nv_bfloat16 g_xh[BN * DMODEL], g_xl[BN * DMODEL];
__device__ __nv_bfloat16 g_wh[3 * DMODEL * DMODEL], g_wl[3 * DMODEL * DMODEL];

// ============================================================
// helpers
// ============================================================
__device__ __forceinline__ uint32_t smem_u32(const void* p) {
    return (uint32_t)__cvta_generic_to_shared(p);
}

__device__ __forceinline__ void cp16(void* smem, const void* gmem) {
    asm volatile("cp.async.cg.shared.global [%0], [%1], 16;\n" ::"r"(smem_u32(smem)),
                 "l"(gmem));
}
#define CP_COMMIT asm volatile("cp.async.commit_group;\n" ::)
#define CP_WAIT0 asm volatile("cp.async.wait_group 0;\n" ::)
#define CP_WAIT1 asm volatile("cp.async.wait_group 1;\n" ::)

__device__ __forceinline__ void ldsm4(uint32_t addr, uint32_t* r) {
    asm volatile("ldmatrix.sync.aligned.m8n8.x4.shared.b16 {%0,%1,%2,%3}, [%4];\n"
                 : "=r"(r[0]), "=r"(r[1]), "=r"(r[2]), "=r"(r[3])
                 : "r"(addr));
}

__device__ __forceinline__ void ldsm4t(uint32_t addr, uint32_t* r) {
    asm volatile("ldmatrix.sync.aligned.m8n8.x4.trans.shared.b16 {%0,%1,%2,%3}, [%4];\n"
                 : "=r"(r[0]), "=r"(r[1]), "=r"(r[2]), "=r"(r[3])
                 : "r"(addr));
}

__device__ __forceinline__ void mma_bf16(float* c, const uint32_t* a, const uint32_t* b) {
    asm volatile(
        "mma.sync.aligned.m16n8k16.row.col.f32.bf16.bf16.f32 "
        "{%0,%1,%2,%3}, {%4,%5,%6,%7}, {%8,%9}, {%0,%1,%2,%3};\n"
        : "+f"(c[0]), "+f"(c[1]), "+f"(c[2]), "+f"(c[3])
        : "r"(a[0]), "r"(a[1]), "r"(a[2]), "r"(a[3]), "r"(b[0]), "r"(b[1]));
}

__device__ __forceinline__ void split2(float v, __nv_bfloat16& h, __nv_bfloat16& l) {
    h = __float2bfloat16(v);
    l = __float2bfloat16(v - __bfloat162float(h));
}

__device__ __forceinline__ uint32_t bpack(__nv_bfloat16 a, __nv_bfloat16 b) {
    __nv_bfloat162 p = __halves2bfloat162(a, b);
    return *reinterpret_cast<uint32_t*>(&p);
}

__device__ __forceinline__ void split_store4(float4 v, __nv_bfloat16* H,
                                             __nv_bfloat16* L) {
    __nv_bfloat16 h0, h1, h2, h3, l0, l1, l2, l3;
    split2(v.x, h0, l0);
    split2(v.y, h1, l1);
    split2(v.z, h2, l2);
    split2(v.w, h3, l3);
    *reinterpret_cast<uint2*>(H) = make_uint2(bpack(h0, h1), bpack(h2, h3));
    *reinterpret_cast<uint2*>(L) = make_uint2(bpack(l0, l1), bpack(l2, l3));
}

// ---- packed f32x2 ops (Blackwell FFMA2 path) ----
__device__ __forceinline__ uint64_t pk2(float lo, float hi) {
    uint64_t d;
    asm("mov.b64 %0, {%1, %2};" : "=l"(d) : "f"(lo), "f"(hi));
    return d;
}
__device__ __forceinline__ void upk2(uint64_t v, float& lo, float& hi) {
    asm("mov.b64 {%0, %1}, %2;" : "=f"(lo), "=f"(hi) : "l"(v));
}
__device__ __forceinline__ uint64_t ffma2(uint64_t a, uint64_t b, uint64_t c) {
    uint64_t d;
    asm("fma.rn.f32x2 %0, %1, %2, %3;" : "=l"(d) : "l"(a), "l"(b), "l"(c));
    return d;
}
__device__ __forceinline__ uint64_t fmul2(uint64_t a, uint64_t b) {
    uint64_t d;
    asm("mul.rn.f32x2 %0, %1, %2;" : "=l"(d) : "l"(a), "l"(b));
    return d;
}

template <int PITCH, int MT>
__device__ __forceinline__ void ldA(const __nv_bfloat16* P, int arow, int acol,
                                    uint32_t a[][4]) {
#pragma unroll
    for (int mt = 0; mt < MT; mt++)
        ldsm4(smem_u32(P + (arow + mt * 16) * PITCH + acol), a[mt]);
}

template <int PITCH, int NP>
__device__ __forceinline__ void ldB(const __nv_bfloat16* P, int brow, int bcol,
                                    uint32_t b[][2]) {
#pragma unroll
    for (int p = 0; p < NP; p++) {
        uint32_t r[4];
        ldsm4(smem_u32(P + (brow + p * 16) * PITCH + bcol), r);
        b[2 * p][0] = r[0];
        b[2 * p][1] = r[1];
        b[2 * p + 1][0] = r[2];
        b[2 * p + 1][1] = r[3];
    }
}

// A fragments via trans: smem holds A^T as [K][m]
template <int PITCH, int MT>
__device__ __forceinline__ void ldAT(const __nv_bfloat16* P, int kc, int m0,
                                     int lane, uint32_t a[][4]) {
    const int row = kc + (lane & 7) + ((lane >> 4) & 1) * 8;
    const int cb = ((lane >> 3) & 1) * 8;
#pragma unroll
    for (int mt = 0; mt < MT; mt++)
        ldsm4t(smem_u32(P + row * PITCH + m0 + mt * 16 + cb), a[mt]);
}

// B fragments via trans: smem holds B as [K][n]
template <int PITCH, int NP>
__device__ __forceinline__ void ldBT(const __nv_bfloat16* P, int kc, int n0,
                                     int lane, uint32_t b[][2]) {
    const int row = kc + (lane & 7) + ((lane >> 3) & 1) * 8;
    const int cb = ((lane >> 4) & 1) * 8;
#pragma unroll
    for (int p = 0; p < NP; p++) {
        uint32_t r[4];
        ldsm4t(smem_u32(P + row * PITCH + n0 + p * 16 + cb), r);
        b[2 * p][0] = r[0];
        b[2 * p][1] = r[1];
        b[2 * p + 1][0] = r[2];
        b[2 * p + 1][1] = r[3];
    }
}

template <int MT, int NT>
__device__ __forceinline__ void mma_tiles(float (*acc)[NT][4], uint32_t a[][4],
                                          uint32_t b[][2]) {
#pragma unroll
    for (int mt = 0; mt < MT; mt++)
#pragma unroll
        for (int nt = 0; nt < NT; nt++) mma_bf16(acc[mt][nt], a[mt], b[nt]);
}

// ============================================================
// Kernel 0a/0b: one-pass fp32 -> bf16 hi/lo plane converters
// Wq pre-scaled by 1/8 so qkv epilogue is scale-free.
// ============================================================
__global__ __launch_bounds__(256) void convert_x_kernel(const float* __restrict__ x,
                                                        int base4) {
    int idx = base4 + blockIdx.x * 256 + threadIdx.x;
    float4 v = *(const float4*)(x + (size_t)idx * 4);
    split_store4(v, g_xh + (size_t)idx * 4, g_xl + (size_t)idx * 4);
}

__global__ __launch_bounds__(256) void convert_w_kernel(
    const float* __restrict__ Wq, const float* __restrict__ Wk,
    const float* __restrict__ Wv) {
    const int z = blockIdx.z;
    const float* __restrict__ W = (z == 0) ? Wq : (z == 1) ? Wk : Wv;
    const float scale = (z == 0) ? 0.125f : 1.0f;
    size_t base = (size_t)z * DMODEL * DMODEL;
    int idx = blockIdx.x * 256 + threadIdx.x;
    float4 v = *(const float4*)(W + (size_t)idx * 4);
    v.x *= scale;
    v.y *= scale;
    v.z *= scale;
    v.w *= scale;
    split_store4(v, g_wh + base + (size_t)idx * 4, g_wl + base + (size_t)idx * 4);
}

// ============================================================
// Kernel 1: QKV projections. CTA 128(m) x 128(n), BK=32,
// 4 warps of 64x64, 128 thr, cp.async double-buffered,
// 2 CTAs/SM for barrier overlap.
// ============================================================
#define P1X 40
#define P1W 136
#define XSTG (128 * P1X)  // 5120 el
#define WSTG (32 * P1W)   // 4352 el
#define QKV_SMEM ((2 * 2 * XSTG + 2 * 2 * WSTG) * 2)  // 75776 B

__global__ __launch_bounds__(128, 2) void qkv_gemm_kernel() {
    extern __shared__ __align__(16) char dynsm[];
    __nv_bfloat16* Xh = (__nv_bfloat16*)dynsm;   // [2][XSTG]
    __nv_bfloat16* Xl = Xh + 2 * XSTG;
    __nv_bfloat16* Wh2 = Xl + 2 * XSTG;          // [2][WSTG]
    __nv_bfloat16* Wl2 = Wh2 + 2 * WSTG;

    const int z = blockIdx.z;
    const __nv_bfloat16* __restrict__ Wh = g_wh + (size_t)z * DMODEL * DMODEL;
    const __nv_bfloat16* __restrict__ Wl = g_wl + (size_t)z * DMODEL * DMODEL;
    __nv_bfloat16* Ch = (z == 0) ? g_qh : (z == 1) ? g_kh : g_vh;
    __nv_bfloat16* Cl = (z == 0) ? g_ql : (z == 1) ? g_kl : g_vl;

    const int m0 = blockIdx.y * 128;
    const int n0 = blockIdx.x * 128;

    const int t = threadIdx.x, lane = t & 31, w = t >> 5;
    const int wm = (w & 1) * 64;   // m: 2 x 64
    const int wn = (w >> 1) * 64;  // n: 2 x 64

    float acc[4][8][4] = {};
    const int arow = wm + (lane & 15);

    auto issue_stage = [&](int s, int kk) {
        // X tile [128 m][32 k]: 512 uint4 per plane, 128 thr -> 4 each
#pragma unroll
        for (int i = 0; i < 4; i++) {
            int e = t + i * 128;
            int r = e >> 2, c = (e & 3) * 8;
            cp16(&Xh[s * XSTG + r * P1X + c], g_xh + (size_t)(m0 + r) * DMODEL + kk + c);
            cp16(&Xl[s * XSTG + r * P1X + c], g_xl + (size_t)(m0 + r) * DMODEL + kk + c);
        }
        // W tile [32 k][128 n]: 512 uint4 per plane, 128 thr -> 4 each
#pragma unroll
        for (int i = 0; i < 4; i++) {
            int e = t + i * 128;
            int r = e >> 4, c = (e & 15) * 8;
            cp16(&Wh2[s * WSTG + r * P1W + c], Wh + (size_t)(kk + r) * DMODEL + n0 + c);
            cp16(&Wl2[s * WSTG + r * P1W + c], Wl + (size_t)(kk + r) * DMODEL + n0 + c);
        }
        CP_COMMIT;
    };

    issue_stage(0, 0);
    const int NIT = DMODEL / 32;  // 24
    for (int it = 0; it < NIT; it++) {
        if (it + 1 < NIT) {
            issue_stage((it + 1) & 1, (it + 1) * 32);
            CP_WAIT1;
        } else {
            CP_WAIT0;
        }
        __syncthreads();

        const __nv_bfloat16* xh = Xh + (it & 1) * XSTG;
        const __nv_bfloat16* xl = Xl + (it & 1) * XSTG;
        const __nv_bfloat16* wh2 = Wh2 + (it & 1) * WSTG;
        const __nv_bfloat16* wl2 = Wl2 + (it & 1) * WSTG;
#pragma unroll
        for (int ks = 0; ks < 2; ks++) {
            const int acol = ks * 16 + (lane >> 4) * 8;
            uint32_t a[4][4], bh[8][2], bl[8][2];
            ldA<P1X, 4>(xh, arow, acol, a);
            ldBT<P1W, 4>(wh2, ks * 16, wn, lane, bh);
            mma_tiles<4, 8>(acc, a, bh);
            ldBT<P1W, 4>(wl2, ks * 16, wn, lane, bl);
            mma_tiles<4, 8>(acc, a, bl);
            ldA<P1X, 4>(xl, arow, acol, a);
            mma_tiles<4, 8>(acc, a, bh);
        }
        __syncthreads();
    }

    const int g = lane >> 2, tig = lane & 3;
#pragma unroll
    for (int mt = 0; mt < 4; mt++) {
        int row = m0 + wm + mt * 16 + g;
#pragma unroll
        for (int nt = 0; nt < 8; nt++) {
            int col = n0 + wn + nt * 8 + 2 * tig;
            __nv_bfloat16 h0, l0, h1, l1;
            split2(acc[mt][nt][0], h0, l0);
            split2(acc[mt][nt][1], h1, l1);
            *(__nv_bfloat162*)(Ch + (size_t)row * DMODEL + col) = __halves2bfloat162(h0, h1);
            *(__nv_bfloat162*)(Cl + (size_t)row * DMODEL + col) = __halves2bfloat162(l0, l1);
            split2(acc[mt][nt][2], h0, l0);
            split2(acc[mt][nt][3], h1, l1);
            *(__nv_bfloat162*)(Ch + (size_t)(row + 8) * DMODEL + col) = __halves2bfloat162(h0, h1);
            *(__nv_bfloat162*)(Cl + (size_t)(row + 8) * DMODEL + col) = __halves2bfloat162(l0, l1);
        }
    }
}

// ============================================================
// Kernel 2: scores for ONE batch. 128x128 tile, K=64 resident.
// 256 thr, 8 warps of 64x32. B-hi kept live. 2 CTAs/SM.
// ============================================================
#define P2 72

__global__ __launch_bounds__(256, 2) void scores_kernel(int b) {
    extern __shared__ __align__(16) __nv_bfloat16 sm2[];
    __nv_bfloat16* Qh = sm2;
    __nv_bfloat16* Ql = Qh + 128 * P2;
    __nv_bfloat16* Kh2 = Ql + 128 * P2;
    __nv_bfloat16* Kl2 = Kh2 + 128 * P2;

    const int h = blockIdx.z;
    const int i0 = blockIdx.y * 128;
    const int j0 = blockIdx.x * 128;

    const int t = threadIdx.x, lane = t & 31, w = t >> 5;
    const int wm = (w & 1) * 64, wn = (w >> 1) * 32;

    const __nv_bfloat16* qhb = g_qh + (size_t)b * SEQ * DMODEL + h * DHEAD;
    const __nv_bfloat16* qlb = g_ql + (size_t)b * SEQ * DMODEL + h * DHEAD;
    const __nv_bfloat16* khb = g_kh + (size_t)b * SEQ * DMODEL + h * DHEAD;
    const __nv_bfloat16* klb = g_kl + (size_t)b * SEQ * DMODEL + h * DHEAD;

#pragma unroll
    for (int e = t; e < 1024; e += 256) {
        int r = e >> 3, c = (e & 7) * 8;
        *(uint4*)&Qh[r * P2 + c] = *(const uint4*)(qhb + (size_t)(i0 + r) * DMODEL + c);
        *(uint4*)&Ql[r * P2 + c] = *(const uint4*)(qlb + (size_t)(i0 + r) * DMODEL + c);
        *(uint4*)&Kh2[r * P2 + c] = *(const uint4*)(khb + (size_t)(j0 + r) * DMODEL + c);
        *(uint4*)&Kl2[r * P2 + c] = *(const uint4*)(klb + (size_t)(j0 + r) * DMODEL + c);
    }
    __syncthreads();

    float acc[4][4][4] = {};
    const int arow = wm + (lane & 15);
    const int bro = wn + (lane & 7) + (lane >> 4) * 8;

#pragma unroll
    for (int ks = 0; ks < 4; ks++) {
        const int acol = ks * 16 + (lane >> 4) * 8;
        const int bcol = ks * 16 + ((lane >> 3) & 1) * 8;
        uint32_t a[4][4], bh[4][2], bl[4][2];
        ldA<P2, 4>(Qh, arow, acol, a);
        ldB<P2, 2>(Kh2, bro, bcol, bh);
        mma_tiles<4, 4>(acc, a, bh);
        ldB<P2, 2>(Kl2, bro, bcol, bl);
        mma_tiles<4, 4>(acc, a, bl);
        ldA<P2, 4>(Ql, arow, acol, a);
        mma_tiles<4, 4>(acc, a, bh);
    }

    float* Sb = g_attn + (size_t)(b * NHEAD + h) * SEQ * SEQ;
    const int g = lane >> 2, tig = lane & 3;
#pragma unroll
    for (int mt = 0; mt < 4; mt++) {
        int row = i0 + wm + mt * 16 + g;
#pragma unroll
        for (int nt = 0; nt < 4; nt++) {
            int col = j0 + wn + nt * 8 + 2 * tig;
            *(float2*)(Sb + (size_t)row * SEQ + col) =
                make_float2(acc[mt][nt][0], acc[mt][nt][1]);
            *(float2*)(Sb + (size_t)(row + 8) * SEQ + col) =
                make_float2(acc[mt][nt][2], acc[mt][nt][3]);
        }
    }
}

// ============================================================
// Kernel 3: softmax (MUFU exp, no max pass) + packed-f32x2 theta
// mix + LN. 256 thr, each owns 4 consecutive k.
// ============================================================
#define NW3 8

template <int V>
__device__ __forceinline__ void blockReduceSumV(float v[V], float* red, float* red2) {
    const int lane = threadIdx.x & 31, w = threadIdx.x >> 5;
#pragma unroll
    for (int h = 0; h < V; h++)
#pragma unroll
        for (int o = 16; o; o >>= 1)
            v[h] += __shfl_xor_sync(0xffffffffu, v[h], o);
    if (lane == 0) {
#pragma unroll
        for (int h = 0; h < V; h++) red[h * NW3 + w] = v[h];
    }
    __syncthreads();
    if (w < V / 4) {
        int val = 4 * w + (lane >> 3);
        float s = red[val * NW3 + (lane & 7)];
#pragma unroll
        for (int o = 4; o; o >>= 1) s += __shfl_xor_sync(0xffffffffu, s, o);
        if ((lane & 7) == 0) red2[val] = s;
    }
    __syncthreads();
#pragma unroll
    for (int h = 0; h < V; h++) v[h] = red2[h];
    __syncthreads();
}

__global__ __launch_bounds__(256) void softmax_theta_ln_kernel(
    int b, const float* __restrict__ theta,
    const float* __restrict__ lnS, const float* __restrict__ lnB) {
    __shared__ uint64_t th2[144];  // theta broadcast-packed (w,w)
    __shared__ float red[24 * NW3];
    __shared__ float red2[24];

    const int qi = blockIdx.x;
    const int t = threadIdx.x;  // owns k = 4t .. 4t+3

    if (t < 144) {
        float wv = theta[t];
        th2[t] = pk2(wv, wv);
    }

    float4 r[NHEAD];
#pragma unroll
    for (int h = 0; h < NHEAD; h++) {
        const float* src = g_attn + ((size_t)(b * NHEAD + h) * SEQ + qi) * SEQ;
        r[h] = *(const float4*)(src + 4 * t);
    }
    float4 s4 = *(const float4*)(lnS + 4 * t);
    float4 b4 = *(const float4*)(lnB + 4 * t);
    __syncthreads();

    // softmax without max subtraction; MUFU exp (overlaps FMA pipe)
    float sum[NHEAD];
#pragma unroll
    for (int h = 0; h < NHEAD; h++) {
        r[h].x = __expf(r[h].x);
        r[h].y = __expf(r[h].y);
        r[h].z = __expf(r[h].z);
        r[h].w = __expf(r[h].w);
        sum[h] = (r[h].x + r[h].y) + (r[h].z + r[h].w);
    }
    blockReduceSumV<12>(sum, red, red2);

    // normalized probabilities, packed as f32x2 pairs
    uint64_t pxy[NHEAD], pzw[NHEAD];
#pragma unroll
    for (int h = 0; h < NHEAD; h++) {
        float inv = 1.0f / sum[h];
        uint64_t inv2 = pk2(inv, inv);
        pxy[h] = fmul2(pk2(r[h].x, r[h].y), inv2);
        pzw[h] = fmul2(pk2(r[h].z, r[h].w), inv2);
    }

    // theta head-mix with packed FFMA2: a_i = sum_h theta[h,i] * p_h
    uint64_t axy[NHEAD], azw[NHEAD];
#pragma unroll
    for (int i = 0; i < NHEAD; i++) {
        uint64_t sx = fmul2(th2[i], pxy[0]);
        uint64_t sz = fmul2(th2[i], pzw[0]);
#pragma unroll
        for (int h = 1; h < NHEAD; h++) {
            sx = ffma2(th2[h * NHEAD + i], pxy[h], sx);
            sz = ffma2(th2[h * NHEAD + i], pzw[h], sz);
        }
        axy[i] = sx;
        azw[i] = sz;
    }

    // LN stats
    float st[24];
#pragma unroll
    for (int i = 0; i < NHEAD; i++) {
        float ax, ay, az, aw;
        upk2(axy[i], ax, ay);
        upk2(azw[i], az, aw);
        st[i] = (ax + ay) + (az + aw);
        st[12 + i] = (ax * ax + ay * ay) + (az * az + aw * aw);
    }
    blockReduceSumV<24>(st, red, red2);

    const uint64_t sxy = pk2(s4.x, s4.y), szw = pk2(s4.z, s4.w);
    const uint64_t bxy = pk2(b4.x, b4.y), bzw = pk2(b4.z, b4.w);

#pragma unroll
    for (int i = 0; i < NHEAD; i++) {
        float mean = st[i] * (1.0f / SEQ);
        float var = st[12 + i] * (1.0f / SEQ) - mean * mean;
        float rstd = rsqrtf(var + 1e-6f);
        float nmr = -mean * rstd;
        uint64_t rstd2 = pk2(rstd, rstd), nmr2 = pk2(nmr, nmr);
        uint64_t txy = ffma2(axy[i], rstd2, nmr2);
        uint64_t tzw = ffma2(azw[i], rstd2, nmr2);
        uint64_t oxy = ffma2(txy, sxy, bxy);
        uint64_t ozw = ffma2(tzw, szw, bzw);
        float4 o;
        upk2(oxy, o.x, o.y);
        upk2(ozw, o.z, o.w);
        size_t off = ((size_t)(b * NHEAD + i) * SEQ + qi) * SEQ + 4 * t;
        split_store4(o, g_ah + off, g_al + off);
    }
}

// ============================================================
// Kernel 4: out (ALL batches). 128(k) x 64(d), q-chunk 32,
// 128 thr, 4 warps of 64(k)x32(d). cp.async double-buffered,
// 2 CTAs/SM for barrier overlap.
// ============================================================
#define PA 136
#define PV 72
#define ASTG (32 * PA)  // 4352 el
#define VSTG (32 * PV)  // 2304 el
#define OUT_SMEM ((2 * 2 * ASTG + 2 * 2 * VSTG) * 2)  // bytes

__global__ __launch_bounds__(128, 2) void out_gemm_kernel(float* __restrict__ out) {
    extern __shared__ __align__(16) char dynsm4[];
    __nv_bfloat16* Ahs = (__nv_bfloat16*)dynsm4;  // [2][ASTG]
    __nv_bfloat16* Als = Ahs + 2 * ASTG;
    __nv_bfloat16* Vhs = Als + 2 * ASTG;          // [2][VSTG]
    __nv_bfloat16* Vls = Vhs + 2 * VSTG;

    const int bh = blockIdx.y;
    const int b = bh / NHEAD, h = bh % NHEAD;
    const int k0b = blockIdx.x * 128;

    const int t = threadIdx.x, lane = t & 31, w = t >> 5;
    const int wm = (w & 1) * 64;   // k-dim
    const int wn = (w >> 1) * 32;  // d-dim

    const __nv_bfloat16* ahb = g_ah + (size_t)(b * NHEAD + h) * SEQ * SEQ;
    const __nv_bfloat16* alb = g_al + (size_t)(b * NHEAD + h) * SEQ * SEQ;
    const __nv_bfloat16* vhb = g_vh + (size_t)b * SEQ * DMODEL + h * DHEAD;
    const __nv_bfloat16* vlb = g_vl + (size_t)b * SEQ * DMODEL + h * DHEAD;

    float acc[4][4][4] = {};

    auto issue_stage = [&](int s, int q0) {
#pragma unroll
        for (int i = 0; i < 4; i++) {
            int idx = t + i * 128;
            int r = idx >> 4, c = (idx & 15) * 8;
            cp16(&Ahs[s * ASTG + r * PA + c], ahb + (size_t)(q0 + r) * SEQ + k0b + c);
            cp16(&Als[s * ASTG + r * PA + c], alb + (size_t)(q0 + r) * SEQ + k0b + c);
        }
#pragma unroll
        for (int i = 0; i < 2; i++) {
            int idx = t + i * 128;
            int r = idx >> 3, c = (idx & 7) * 8;
            cp16(&Vhs[s * VSTG + r * PV + c], vhb + (size_t)(q0 + r) * DMODEL + c);
            cp16(&Vls[s * VSTG + r * PV + c], vlb + (size_t)(q0 + r) * DMODEL + c);
        }
        CP_COMMIT;
    };

    issue_stage(0, 0);
    const int NIT = SEQ / 32;  // 32
    for (int it = 0; it < NIT; it++) {
        if (it + 1 < NIT) {
            issue_stage((it + 1) & 1, (it + 1) * 32);
            CP_WAIT1;
        } else {
            CP_WAIT0;
        }
        __syncthreads();

        const __nv_bfloat16* ah = Ahs + (it & 1) * ASTG;
        const __nv_bfloat16* al = Als + (it & 1) * ASTG;
        const __nv_bfloat16* vh = Vhs + (it & 1) * VSTG;
        const __nv_bfloat16* vl = Vls + (it & 1) * VSTG;
#pragma unroll
        for (int ks = 0; ks < 2; ks++) {
            const int qc = ks * 16;
            uint32_t a[4][4], bh2[4][2], bl2[4][2];
            ldAT<PA, 4>(ah, qc, wm, lane, a);
            ldBT<PV, 2>(vh, qc, wn, lane, bh2);
            mma_tiles<4, 4>(acc, a, bh2);
            ldBT<PV, 2>(vl, qc, wn, lane, bl2);
            mma_tiles<4, 4>(acc, a, bl2);
            ldAT<PA, 4>(al, qc, wm, lane, a);
            mma_tiles<4, 4>(acc, a, bh2);
        }
        __syncthreads();
    }

    const int g = lane >> 2, tig = lane & 3;
#pragma unroll
    for (int mt = 0; mt < 4; mt++) {
        int row = k0b + wm + mt * 16 + g;
#pragma unroll
        for (int nt = 0; nt < 4; nt++) {
            int col = h * DHEAD + wn + nt * 8 + 2 * tig;
            *(float2*)(out + (size_t)(b * SEQ + row) * DMODEL + col) =
                make_float2(acc[mt][nt][0], acc[mt][nt][1]);
            *(float2*)(out + (size_t)(b * SEQ + row + 8) * DMODEL + col) =
                make_float2(acc[mt][nt][2], acc[mt][nt][3]);
        }
    }
}

// ============================================================
extern "C" void kernel_launch(void* const* d_in, const int* in_sizes, int n_in,
                              void* d_out, int out_size) {
    const float* x     = (const float*)d_in[0];
    const float* Wq    = (const float*)d_in[1];
    const float* Wk    = (const float*)d_in[2];
    const float* Wv    = (const float*)d_in[3];
    const float* theta = (const float*)d_in[4];
    const float* lnS   = (const float*)d_in[5];
    const float* lnB   = (const float*)d_in[6];
    float* out = (float*)d_out;

    // 0. convert inputs to bf16 hi/lo planes (Wq pre-scaled by 1/8).
    const int X4 = BN * DMODEL / 4;
    convert_x_kernel<<<X4 / 2 / 256, 256>>>(x, 0);
    convert_x_kernel<<<X4 / 2 / 256, 256>>>(x, X4 / 2);
    {
        dim3 grid(DMODEL * DMODEL / 4 / 256, 1, 3);
        convert_w_kernel<<<grid, 256>>>(Wq, Wk, Wv);
    }
    // 1. QKV projections (128x128 CTA, 4 warps of 64x64, 2 CTA/SM)
    {
        cudaFuncSetAttribute(qkv_gemm_kernel,
                             cudaFuncAttributeMaxDynamicSharedMemorySize, QKV_SMEM);
        dim3 grid(DMODEL / 128, BN / 128, 3);
        qkv_gemm_kernel<<<grid, 128, QKV_SMEM>>>();
    }
    // 2-3. per-batch scores -> softmax pairs: S (48 MB/batch) stays in L2
    int smem = 4 * 128 * P2 * sizeof(__nv_bfloat16);  // 73728 B
    cudaFuncSetAttribute(scores_kernel,
                         cudaFuncAttributeMaxDynamicSharedMemorySize, smem);
    for (int b = 0; b < BATCH; b++) {
        dim3 grid2(SEQ / 128, SEQ / 128, NHEAD);
        scores_kernel<<<grid2, 256, smem>>>(b);
        softmax_theta_ln_kernel<<<SEQ, 256>>>(b, theta, lnS, lnB);
    }
    // 4. output GEMM, full batch (384 CTAs), cp.async, 2 CTA/SM
    {
        cudaFuncSetAttribute(out_gemm_kernel,
                             cudaFuncAttributeMaxDynamicSharedMemorySize, OUT_SMEM);
        dim3 grid4(SEQ / 128, BATCH * NHEAD);
        out_gemm_kernel<<<grid4, 128, OUT_SMEM>>>(out);
    }
}